// round 7
// baseline (speedup 1.0000x reference)
#include <cuda_runtime.h>
#include <cuda_bf16.h>
#include <math.h>
#include <stdint.h>

#define NB   4
#define NS   2048
#define ND   1024
#define NH   16
#define NDH  64
#define MT   (NB*NS)          // 8192 rows
#define QKV_ELEMS ((size_t)NB*NH*NS*NDH)

// ---------------- scratch (device globals: no allocation allowed) ----------
__device__ float g_Q[QKV_ELEMS];              // fp32 pre-RoPE
__device__ float g_K[QKV_ELEMS];
__device__ __nv_bfloat16 g_Qh[QKV_ELEMS], g_Ql[QKV_ELEMS];   // post-RoPE, *0.125
__device__ __nv_bfloat16 g_Kh[QKV_ELEMS], g_Kl[QKV_ELEMS];
__device__ __nv_bfloat16 g_Vh[QKV_ELEMS], g_Vl[QKV_ELEMS];
__device__ __nv_bfloat16 g_xh[(size_t)MT*ND],   g_xl[(size_t)MT*ND];
__device__ __nv_bfloat16 g_wqh[(size_t)3*ND*ND], g_wql[(size_t)3*ND*ND];
__device__ __nv_bfloat16 g_woh[(size_t)ND*ND],  g_wol[(size_t)ND*ND];
__device__ __nv_bfloat16 g_ctxh[(size_t)MT*ND], g_ctxl[(size_t)MT*ND];

// ======================= helpers ===========================================
__device__ __forceinline__ uint32_t smem_u32(const void* p) {
    uint32_t a;
    asm("{ .reg .u64 t; cvta.to.shared.u64 t, %1; cvt.u32.u64 %0, t; }"
        : "=r"(a) : "l"(p));
    return a;
}
__device__ __forceinline__ void ldmx4(uint32_t addr, uint32_t r[4]) {
    asm volatile("ldmatrix.sync.aligned.m8n8.x4.shared.b16 {%0,%1,%2,%3}, [%4];"
                 : "=r"(r[0]), "=r"(r[1]), "=r"(r[2]), "=r"(r[3]) : "r"(addr));
}
__device__ __forceinline__ void ldmx4t(uint32_t addr, uint32_t r[4]) {
    asm volatile("ldmatrix.sync.aligned.m8n8.x4.trans.shared.b16 {%0,%1,%2,%3}, [%4];"
                 : "=r"(r[0]), "=r"(r[1]), "=r"(r[2]), "=r"(r[3]) : "r"(addr));
}
__device__ __forceinline__ void mma16816(float c[4], const uint32_t a[4],
                                         uint32_t b0, uint32_t b1) {
    asm("mma.sync.aligned.m16n8k16.row.col.f32.bf16.bf16.f32 "
        "{%0,%1,%2,%3}, {%4,%5,%6,%7}, {%8,%9}, {%0,%1,%2,%3};"
        : "+f"(c[0]), "+f"(c[1]), "+f"(c[2]), "+f"(c[3])
        : "r"(a[0]), "r"(a[1]), "r"(a[2]), "r"(a[3]), "r"(b0), "r"(b1));
}
__device__ __forceinline__ void split2(float x, float y, uint32_t& hi, uint32_t& lo) {
    __nv_bfloat162 h = __floats2bfloat162_rn(x, y);
    hi = *(uint32_t*)&h;
    __nv_bfloat162 l = __floats2bfloat162_rn(x - __bfloat162float(h.x),
                                             y - __bfloat162float(h.y));
    lo = *(uint32_t*)&l;
}
// XOR swizzle: 16B chunk c of 64B row
__device__ __forceinline__ uint32_t swz(int row, int c) {
    return (uint32_t)(row * 64 + ((c ^ ((row >> 1) & 3)) * 16));
}
// XOR swizzle for 128B rows
__device__ __forceinline__ uint32_t swz128(int row, int c) {
    return (uint32_t)(row * 128 + ((c ^ (row & 7)) * 16));
}
__device__ __forceinline__ void cpa16(uint32_t dst, const void* src) {
    asm volatile("cp.async.cg.shared.global [%0], [%1], 16;"
                 :: "r"(dst), "l"(src));
}
#define CP_COMMIT()  asm volatile("cp.async.commit_group;")
#define CP_WAIT(n)   asm volatile("cp.async.wait_group %0;" :: "n"(n))

// ===========================================================================
// split fp32 array into bf16 hi/lo
// ===========================================================================
__global__ void conv_split(const float4* __restrict__ in,
                           uint2* __restrict__ hi, uint2* __restrict__ lo, int n4)
{
    int i = blockIdx.x * blockDim.x + threadIdx.x;
    if (i >= n4) return;
    float4 v = in[i];
    uint32_t h0, l0, h1, l1;
    split2(v.x, v.y, h0, l0);
    split2(v.z, v.w, h1, l1);
    hi[i] = make_uint2(h0, h1);
    lo[i] = make_uint2(l0, l1);
}

// ===========================================================================
// bf16 3-term GEMM (unchanged from R5/R6 passing version).
// ===========================================================================
#define GSTG 32768
#define GK_SMEM (4*GSTG)

template<int EPI>
__global__ __launch_bounds__(256, 1) void gemm_bf16(
    const __nv_bfloat16* __restrict__ Ah, const __nv_bfloat16* __restrict__ Al,
    const __nv_bfloat16* __restrict__ Wh, const __nv_bfloat16* __restrict__ Wl,
    const float* __restrict__ bias, float* __restrict__ C, int N, int K)
{
    extern __shared__ char smc[];
    const uint32_t sb = smem_u32(smc);

    const int tid  = threadIdx.x;
    const int warp = tid >> 5, lane = tid & 31;
    const int wm = warp & 3, cg = warp >> 2;
    const int m0 = blockIdx.y * 128, n0 = blockIdx.x * 128;

    const int rowA = tid >> 2, cA = tid & 3;
    const int rowB = (tid + 256) >> 2, cB = tid & 3;
    const uint32_t offA = swz(rowA, cA), offB = swz(rowB, cB);
    const __nv_bfloat16* pAhA = Ah + (size_t)(m0 + rowA) * K + cA * 8;
    const __nv_bfloat16* pAlA = Al + (size_t)(m0 + rowA) * K + cA * 8;
    const __nv_bfloat16* pWhA = Wh + (size_t)(n0 + rowA) * K + cA * 8;
    const __nv_bfloat16* pWlA = Wl + (size_t)(n0 + rowA) * K + cA * 8;
    const __nv_bfloat16* pAhB = Ah + (size_t)(m0 + rowB) * K + cB * 8;
    const __nv_bfloat16* pAlB = Al + (size_t)(m0 + rowB) * K + cB * 8;
    const __nv_bfloat16* pWhB = Wh + (size_t)(n0 + rowB) * K + cB * 8;
    const __nv_bfloat16* pWlB = Wl + (size_t)(n0 + rowB) * K + cB * 8;

    float acc[2][8][4];
    #pragma unroll
    for (int mt = 0; mt < 2; mt++)
        #pragma unroll
        for (int nt = 0; nt < 8; nt++)
            #pragma unroll
            for (int i = 0; i < 4; i++) acc[mt][nt][i] = 0.f;

    uint32_t aOff[2][2], bOff[2][4];
    #pragma unroll
    for (int h = 0; h < 2; h++) {
        #pragma unroll
        for (int mt = 0; mt < 2; mt++) {
            int r = wm * 32 + mt * 16 + (lane & 15);
            int c = h * 2 + ((lane >> 4) & 1);
            aOff[h][mt] = swz(r, c);
        }
        #pragma unroll
        for (int ntp = 0; ntp < 4; ntp++) {
            int r = cg * 64 + ntp * 16 + (lane & 7) + ((lane >> 4) & 1) * 8;
            int c = h * 2 + ((lane >> 3) & 1);
            bOff[h][ntp] = swz(r, c);
        }
    }

    const int NSTG = K / 32;

    auto issue = [&](int s) {
        const uint32_t base = sb + (s & 3) * GSTG;
        const int k0 = s * 32;
        cpa16(base + offA,         pAhA + k0);
        cpa16(base + 8192  + offA, pAlA + k0);
        cpa16(base + 16384 + offA, pWhA + k0);
        cpa16(base + 24576 + offA, pWlA + k0);
        cpa16(base + offB,         pAhB + k0);
        cpa16(base + 8192  + offB, pAlB + k0);
        cpa16(base + 16384 + offB, pWhB + k0);
        cpa16(base + 24576 + offB, pWlB + k0);
    };

    issue(0); CP_COMMIT();
    issue(1); CP_COMMIT();
    issue(2); CP_COMMIT();

    for (int s = 0; s < NSTG; s++) {
        CP_WAIT(2);
        __syncthreads();
        if (s + 3 < NSTG) issue(s + 3);
        CP_COMMIT();

        const uint32_t base = sb + (s & 3) * GSTG;
        #pragma unroll
        for (int h = 0; h < 2; h++) {
            uint32_t ah[2][4], al[2][4];
            #pragma unroll
            for (int mt = 0; mt < 2; mt++) {
                ldmx4(base + aOff[h][mt], ah[mt]);
                ldmx4(base + 8192 + aOff[h][mt], al[mt]);
            }
            #pragma unroll
            for (int ntp = 0; ntp < 4; ntp++) {
                uint32_t bh[4], bl[4];
                ldmx4(base + 16384 + bOff[h][ntp], bh);
                ldmx4(base + 24576 + bOff[h][ntp], bl);
                mma16816(acc[0][2*ntp],   ah[0], bh[0], bh[1]);
                mma16816(acc[0][2*ntp+1], ah[0], bh[2], bh[3]);
                mma16816(acc[1][2*ntp],   ah[1], bh[0], bh[1]);
                mma16816(acc[1][2*ntp+1], ah[1], bh[2], bh[3]);
                mma16816(acc[0][2*ntp],   ah[0], bl[0], bl[1]);
                mma16816(acc[0][2*ntp+1], ah[0], bl[2], bl[3]);
                mma16816(acc[1][2*ntp],   ah[1], bl[0], bl[1]);
                mma16816(acc[1][2*ntp+1], ah[1], bl[2], bl[3]);
                mma16816(acc[0][2*ntp],   al[0], bh[0], bh[1]);
                mma16816(acc[0][2*ntp+1], al[0], bh[2], bh[3]);
                mma16816(acc[1][2*ntp],   al[1], bh[0], bh[1]);
                mma16816(acc[1][2*ntp+1], al[1], bh[2], bh[3]);
            }
        }
    }

    const int g = lane >> 2, tig = lane & 3;
    const int nBase = n0 + cg * 64;

    float bcol[8][2];
    #pragma unroll
    for (int nt = 0; nt < 8; nt++) {
        bcol[nt][0] = bias[nBase + nt * 8 + tig * 2];
        bcol[nt][1] = bias[nBase + nt * 8 + tig * 2 + 1];
    }

    if (EPI == 0) {
        int part = nBase >> 10;
        int hd   = (nBase & 1023) >> 6;
        #pragma unroll
        for (int mt = 0; mt < 2; mt++)
            #pragma unroll
            for (int half = 0; half < 2; half++) {
                int m = m0 + wm * 32 + mt * 16 + g + half * 8;
                int b = m >> 11, sq = m & 2047;
                size_t rb = (((size_t)b * NH + hd) * NS + sq) * NDH;
                if (part < 2) {
                    float* dst = part ? g_K : g_Q;
                    #pragma unroll
                    for (int nt = 0; nt < 8; nt++) {
                        int d = nt * 8 + tig * 2;
                        float2 v;
                        v.x = acc[mt][nt][half*2]   + bcol[nt][0];
                        v.y = acc[mt][nt][half*2+1] + bcol[nt][1];
                        *(float2*)(dst + rb + d) = v;
                    }
                } else {
                    #pragma unroll
                    for (int nt = 0; nt < 8; nt++) {
                        int d = nt * 8 + tig * 2;
                        float vx = acc[mt][nt][half*2]   + bcol[nt][0];
                        float vy = acc[mt][nt][half*2+1] + bcol[nt][1];
                        uint32_t hi, lo;
                        split2(vx, vy, hi, lo);
                        *(uint32_t*)((char*)g_Vh + (rb + d) * 2) = hi;
                        *(uint32_t*)((char*)g_Vl + (rb + d) * 2) = lo;
                    }
                }
            }
    } else {
        #pragma unroll
        for (int mt = 0; mt < 2; mt++)
            #pragma unroll
            for (int half = 0; half < 2; half++) {
                int m = m0 + wm * 32 + mt * 16 + g + half * 8;
                #pragma unroll
                for (int nt = 0; nt < 8; nt++) {
                    int n = nBase + nt * 8 + tig * 2;
                    float2 v;
                    v.x = acc[mt][nt][half*2]   + bcol[nt][0];
                    v.y = acc[mt][nt][half*2+1] + bcol[nt][1];
                    *(float2*)(C + (size_t)m * N + n) = v;
                }
            }
    }
}

// ===========================================================================
// RoPE: read fp32 Q/K, rotate, write bf16 hi/lo (Q pre-scaled by 0.125).
// ===========================================================================
__global__ void rope_split(const int* __restrict__ p)
{
    int idx = blockIdx.x * blockDim.x + threadIdx.x;
    if (idx >= NB*NH*NS*32) return;
    int i = idx & 31;
    int t = idx >> 5;
    int s = t & (NS - 1);
    int b = t >> 15;
    int pos = p[b * NS + s];

    float f = (float)exp(-(double)i * (9.210340371976184 / 32.0));
    float ang = (float)pos * f;
    float c, sn;
    sincosf(ang, &sn, &c);

    size_t base = (size_t)t * NDH;
    float q1 = g_Q[base + i], q2 = g_Q[base + i + 32];
    float rq1 = (q1 * c + q2 * sn) * 0.125f;
    float rq2 = (q2 * c - q1 * sn) * 0.125f;
    float k1 = g_K[base + i], k2 = g_K[base + i + 32];
    float rk1 = k1 * c + k2 * sn;
    float rk2 = k2 * c - k1 * sn;

    __nv_bfloat16 h;
    h = __float2bfloat16_rn(rq1);
    g_Qh[base + i] = h;      g_Ql[base + i]      = __float2bfloat16_rn(rq1 - __bfloat162float(h));
    h = __float2bfloat16_rn(rq2);
    g_Qh[base + i + 32] = h; g_Ql[base + i + 32] = __float2bfloat16_rn(rq2 - __bfloat162float(h));
    h = __float2bfloat16_rn(rk1);
    g_Kh[base + i] = h;      g_Kl[base + i]      = __float2bfloat16_rn(rk1 - __bfloat162float(h));
    h = __float2bfloat16_rn(rk2);
    g_Kh[base + i + 32] = h; g_Kl[base + i + 32] = __float2bfloat16_rn(rk2 - __bfloat162float(h));
}

// ===========================================================================
// Tensor-core flash attention: 256 threads / 8 warps, 128 q per CTA,
// each warp owns 16 queries. Pre-split bf16, cp.async double-buffered K/V.
// ===========================================================================
#define AQ_H 0
#define AQ_L 16384
#define ASTG_BASE 32768
#define ASTG 32768
#define AT_SMEM (ASTG_BASE + 2*ASTG)    // 98304

__global__ __launch_bounds__(256, 2) void attn_mma()
{
    extern __shared__ char sma[];
    const uint32_t sb = smem_u32(sma);

    const int tid = threadIdx.x;
    const int warp = tid >> 5, lane = tid & 31;
    const int qt = blockIdx.x, bh = blockIdx.y;

    const size_t qbase  = ((size_t)bh * NS + qt * 128) * NDH;
    const size_t kvbase = (size_t)bh * NS * NDH;

    // ---- Q fill (cp.async): 128 rows x 8 chunks, hi+lo --------------------
    {
        #pragma unroll
        for (int j = 0; j < 4; j++) {
            int idx = tid + j * 256;
            int row = idx >> 3, c = idx & 7;
            uint32_t o = swz128(row, c);
            size_t go = qbase + (size_t)row * NDH + c * 8;
            cpa16(sb + AQ_H + o, g_Qh + go);
            cpa16(sb + AQ_L + o, g_Ql + go);
        }
        CP_COMMIT();
    }

    // K/V stage issue: 64 rows x 8 chunks x 4 arrays, 256 threads -> 8 each
    const int rKV = tid >> 3, cKV = tid & 7;     // rows 0..31 base
    auto issue_kv = [&](int kt) {
        const uint32_t base = sb + ASTG_BASE + (kt & 1) * ASTG;
        #pragma unroll
        for (int j = 0; j < 2; j++) {
            int row = rKV + j * 32;
            uint32_t o = swz128(row, cKV);
            size_t go = kvbase + (size_t)(kt * 64 + row) * NDH + cKV * 8;
            cpa16(base + o,         g_Kh + go);
            cpa16(base + 8192  + o, g_Kl + go);
            cpa16(base + 16384 + o, g_Vh + go);
            cpa16(base + 24576 + o, g_Vl + go);
        }
    };
    issue_kv(0); CP_COMMIT();

    // ---- fragment smem offsets --------------------------------------------
    uint32_t qOff[4];
    #pragma unroll
    for (int kc = 0; kc < 4; kc++) {
        int r = warp * 16 + (lane & 15);
        int c = kc * 2 + ((lane >> 4) & 1);
        qOff[kc] = swz128(r, c);
    }
    uint32_t kOff[4][4];
    #pragma unroll
    for (int kc = 0; kc < 4; kc++)
        #pragma unroll
        for (int ntp = 0; ntp < 4; ntp++) {
            int r = ntp * 16 + (lane & 7) + ((lane >> 4) & 1) * 8;
            int c = kc * 2 + ((lane >> 3) & 1);
            kOff[kc][ntp] = swz128(r, c);
        }
    uint32_t vOff[4][4];
    #pragma unroll
    for (int kq = 0; kq < 4; kq++)
        #pragma unroll
        for (int dp = 0; dp < 4; dp++) {
            int r = kq * 16 + (lane & 7) + ((lane >> 3) & 1) * 8;
            int c = dp * 2 + ((lane >> 4) & 1);
            vOff[kq][dp] = swz128(r, c);
        }

    float Oa[8][4];
    float mrun[2], lrun[2];
    mrun[0] = -INFINITY; mrun[1] = -INFINITY;
    lrun[0] = 0.f;       lrun[1] = 0.f;
    #pragma unroll
    for (int dt = 0; dt < 8; dt++)
        #pragma unroll
        for (int i = 0; i < 4; i++) Oa[dt][i] = 0.f;

    for (int kt = 0; kt < NS / 64; kt++) {
        CP_WAIT(0);
        __syncthreads();
        if (kt + 1 < NS / 64) issue_kv(kt + 1);
        CP_COMMIT();

        const uint32_t kb = sb + ASTG_BASE + (kt & 1) * ASTG;

        // ---- S = Q K^T (3-term) -------------------------------------------
        float S[8][4];
        #pragma unroll
        for (int nt = 0; nt < 8; nt++)
            #pragma unroll
            for (int i = 0; i < 4; i++) S[nt][i] = 0.f;

        #pragma unroll
        for (int kc = 0; kc < 4; kc++) {
            uint32_t qh[4], ql[4];
            ldmx4(sb + AQ_H + qOff[kc], qh);
            ldmx4(sb + AQ_L + qOff[kc], ql);
            #pragma unroll
            for (int ntp = 0; ntp < 4; ntp++) {
                uint32_t kh[4], kl[4];
                ldmx4(kb + kOff[kc][ntp], kh);
                ldmx4(kb + 8192 + kOff[kc][ntp], kl);
                mma16816(S[2*ntp],   qh, kh[0], kh[1]);
                mma16816(S[2*ntp+1], qh, kh[2], kh[3]);
                mma16816(S[2*ntp],   qh, kl[0], kl[1]);
                mma16816(S[2*ntp+1], qh, kl[2], kl[3]);
                mma16816(S[2*ntp],   ql, kh[0], kh[1]);
                mma16816(S[2*ntp+1], ql, kh[2], kh[3]);
            }
        }

        // ---- online softmax -----------------------------------------------
        {
            float mx0 = -INFINITY, mx1 = -INFINITY;
            #pragma unroll
            for (int j = 0; j < 8; j++) {
                mx0 = fmaxf(mx0, fmaxf(S[j][0], S[j][1]));
                mx1 = fmaxf(mx1, fmaxf(S[j][2], S[j][3]));
            }
            mx0 = fmaxf(mx0, __shfl_xor_sync(0xffffffffu, mx0, 1));
            mx0 = fmaxf(mx0, __shfl_xor_sync(0xffffffffu, mx0, 2));
            mx1 = fmaxf(mx1, __shfl_xor_sync(0xffffffffu, mx1, 1));
            mx1 = fmaxf(mx1, __shfl_xor_sync(0xffffffffu, mx1, 2));
            float nm0 = fmaxf(mrun[0], mx0);
            float nm1 = fmaxf(mrun[1], mx1);
            float a0 = __expf(mrun[0] - nm0);
            float a1 = __expf(mrun[1] - nm1);
            mrun[0] = nm0; mrun[1] = nm1;
            float s0 = 0.f, s1 = 0.f;
            #pragma unroll
            for (int j = 0; j < 8; j++) {
                S[j][0] = __expf(S[j][0] - nm0); s0 += S[j][0];
                S[j][1] = __expf(S[j][1] - nm0); s0 += S[j][1];
                S[j][2] = __expf(S[j][2] - nm1); s1 += S[j][2];
                S[j][3] = __expf(S[j][3] - nm1); s1 += S[j][3];
            }
            s0 += __shfl_xor_sync(0xffffffffu, s0, 1);
            s0 += __shfl_xor_sync(0xffffffffu, s0, 2);
            s1 += __shfl_xor_sync(0xffffffffu, s1, 1);
            s1 += __shfl_xor_sync(0xffffffffu, s1, 2);
            lrun[0] = lrun[0] * a0 + s0;
            lrun[1] = lrun[1] * a1 + s1;
            #pragma unroll
            for (int dt = 0; dt < 8; dt++) {
                Oa[dt][0] *= a0; Oa[dt][1] *= a0;
                Oa[dt][2] *= a1; Oa[dt][3] *= a1;
            }
        }

        // ---- O += P V (3-term) --------------------------------------------
        #pragma unroll
        for (int kq = 0; kq < 4; kq++) {
            uint32_t pah[4], pal[4];
            split2(S[2*kq][0],   S[2*kq][1],   pah[0], pal[0]);
            split2(S[2*kq][2],   S[2*kq][3],   pah[1], pal[1]);
            split2(S[2*kq+1][0], S[2*kq+1][1], pah[2], pal[2]);
            split2(S[2*kq+1][2], S[2*kq+1][3], pah[3], pal[3]);
            #pragma unroll
            for (int dp = 0; dp < 4; dp++) {
                uint32_t vh[4], vl[4];
                ldmx4t(kb + 16384 + vOff[kq][dp], vh);
                ldmx4t(kb + 24576 + vOff[kq][dp], vl);
                mma16816(Oa[2*dp],   pah, vh[0], vh[1]);
                mma16816(Oa[2*dp+1], pah, vh[2], vh[3]);
                mma16816(Oa[2*dp],   pah, vl[0], vl[1]);
                mma16816(Oa[2*dp+1], pah, vl[2], vl[3]);
                mma16816(Oa[2*dp],   pal, vh[0], vh[1]);
                mma16816(Oa[2*dp+1], pal, vh[2], vh[3]);
            }
        }
    }

    // ---- epilogue: O /= l -> ctx hi/lo bf16 [B,S,H*Dh] --------------------
    const int b = bh >> 4, h = bh & 15;
    const int g = lane >> 2, tg = lane & 3;
    #pragma unroll
    for (int half = 0; half < 2; half++) {
        int q = qt * 128 + warp * 16 + g + half * 8;
        float inv = 1.0f / lrun[half];
        size_t rb = ((size_t)b * NS + q) * ND + h * NDH;
        #pragma unroll
        for (int dt = 0; dt < 8; dt++) {
            float vx = Oa[dt][half*2]   * inv;
            float vy = Oa[dt][half*2+1] * inv;
            uint32_t hi, lo;
            split2(vx, vy, hi, lo);
            size_t o = rb + dt * 8 + tg * 2;
            *(uint32_t*)((char*)g_ctxh + o * 2) = hi;
            *(uint32_t*)((char*)g_ctxl + o * 2) = lo;
        }
    }
}

// ===========================================================================
extern "C" void kernel_launch(void* const* d_in, const int* in_sizes, int n_in,
                              void* d_out, int out_size)
{
    (void)in_sizes; (void)n_in; (void)out_size;
    const float* x      = (const float*)d_in[0];
    const int*   p      = (const int*)d_in[1];
    const float* Wqkv_w = (const float*)d_in[2];
    const float* Wqkv_b = (const float*)d_in[3];
    const float* Wo_w   = (const float*)d_in[4];
    const float* Wo_b   = (const float*)d_in[5];
    float* out = (float*)d_out;

    cudaFuncSetAttribute(gemm_bf16<0>,
                         cudaFuncAttributeMaxDynamicSharedMemorySize, GK_SMEM);
    cudaFuncSetAttribute(gemm_bf16<1>,
                         cudaFuncAttributeMaxDynamicSharedMemorySize, GK_SMEM);
    cudaFuncSetAttribute(attn_mma,
                         cudaFuncAttributeMaxDynamicSharedMemorySize, AT_SMEM);

    __nv_bfloat16 *xh, *xl, *wqh, *wql, *woh, *wol, *ctxh, *ctxl;
    cudaGetSymbolAddress((void**)&xh,  g_xh);  cudaGetSymbolAddress((void**)&xl,  g_xl);
    cudaGetSymbolAddress((void**)&wqh, g_wqh); cudaGetSymbolAddress((void**)&wql, g_wql);
    cudaGetSymbolAddress((void**)&woh, g_woh); cudaGetSymbolAddress((void**)&wol, g_wol);
    cudaGetSymbolAddress((void**)&ctxh, g_ctxh); cudaGetSymbolAddress((void**)&ctxl, g_ctxl);

    int n4x = MT * ND / 4, n4wq = 3 * ND * ND / 4, n4wo = ND * ND / 4;
    conv_split<<<(n4x  + 255) / 256, 256>>>((const float4*)x,      (uint2*)xh,  (uint2*)xl,  n4x);
    conv_split<<<(n4wq + 255) / 256, 256>>>((const float4*)Wqkv_w, (uint2*)wqh, (uint2*)wql, n4wq);
    conv_split<<<(n4wo + 255) / 256, 256>>>((const float4*)Wo_w,   (uint2*)woh, (uint2*)wol, n4wo);

    dim3 g1(3 * ND / 128, MT / 128);
    gemm_bf16<0><<<g1, 256, GK_SMEM>>>(xh, xl, wqh, wql, Wqkv_b, nullptr, 3 * ND, ND);

    int nrope = NB * NH * NS * 32;
    rope_split<<<(nrope + 255) / 256, 256>>>(p);

    attn_mma<<<dim3(NS / 128, NB * NH), 256, AT_SMEM>>>();

    dim3 g2(ND / 128, MT / 128);
    gemm_bf16<1><<<g2, 256, GK_SMEM>>>(ctxh, ctxl, woh, wol, Wo_b, out, ND, ND);
}

// round 8
// speedup vs baseline: 2.0583x; 2.0583x over previous
#include <cuda_runtime.h>
#include <cuda_fp16.h>
#include <math.h>
#include <stdint.h>

#define NB   4
#define NS   2048
#define ND   1024
#define NH   16
#define NDH  64
#define MT   (NB*NS)          // 8192 rows
#define QKV_ELEMS ((size_t)NB*NH*NS*NDH)

// ---------------- scratch (device globals: no allocation allowed) ----------
__device__ float g_Q[QKV_ELEMS];              // fp32 pre-RoPE
__device__ float g_K[QKV_ELEMS];
__device__ __half g_Qhf[QKV_ELEMS];           // post-RoPE, *0.125, fp16
__device__ __half g_Khf[QKV_ELEMS];
__device__ __half g_Vhf[QKV_ELEMS];
__device__ __half g_xhf[(size_t)MT*ND];
__device__ __half g_wqhf[(size_t)3*ND*ND];
__device__ __half g_wohf[(size_t)ND*ND];
__device__ __half g_ctxhf[(size_t)MT*ND];

// ======================= helpers ===========================================
__device__ __forceinline__ uint32_t smem_u32(const void* p) {
    uint32_t a;
    asm("{ .reg .u64 t; cvta.to.shared.u64 t, %1; cvt.u32.u64 %0, t; }"
        : "=r"(a) : "l"(p));
    return a;
}
__device__ __forceinline__ void ldmx4(uint32_t addr, uint32_t r[4]) {
    asm volatile("ldmatrix.sync.aligned.m8n8.x4.shared.b16 {%0,%1,%2,%3}, [%4];"
                 : "=r"(r[0]), "=r"(r[1]), "=r"(r[2]), "=r"(r[3]) : "r"(addr));
}
__device__ __forceinline__ void ldmx4t(uint32_t addr, uint32_t r[4]) {
    asm volatile("ldmatrix.sync.aligned.m8n8.x4.trans.shared.b16 {%0,%1,%2,%3}, [%4];"
                 : "=r"(r[0]), "=r"(r[1]), "=r"(r[2]), "=r"(r[3]) : "r"(addr));
}
__device__ __forceinline__ void mma16816(float c[4], const uint32_t a[4],
                                         uint32_t b0, uint32_t b1) {
    asm("mma.sync.aligned.m16n8k16.row.col.f32.f16.f16.f32 "
        "{%0,%1,%2,%3}, {%4,%5,%6,%7}, {%8,%9}, {%0,%1,%2,%3};"
        : "+f"(c[0]), "+f"(c[1]), "+f"(c[2]), "+f"(c[3])
        : "r"(a[0]), "r"(a[1]), "r"(a[2]), "r"(a[3]), "r"(b0), "r"(b1));
}
__device__ __forceinline__ uint32_t packh2(float x, float y) {
    __half2 h = __floats2half2_rn(x, y);
    return *(uint32_t*)&h;
}
// XOR swizzle: 16B chunk c of 64B row
__device__ __forceinline__ uint32_t swz(int row, int c) {
    return (uint32_t)(row * 64 + ((c ^ ((row >> 1) & 3)) * 16));
}
// XOR swizzle for 128B rows
__device__ __forceinline__ uint32_t swz128(int row, int c) {
    return (uint32_t)(row * 128 + ((c ^ (row & 7)) * 16));
}
__device__ __forceinline__ void cpa16(uint32_t dst, const void* src) {
    asm volatile("cp.async.cg.shared.global [%0], [%1], 16;"
                 :: "r"(dst), "l"(src));
}
#define CP_COMMIT()  asm volatile("cp.async.commit_group;")
#define CP_WAIT(n)   asm volatile("cp.async.wait_group %0;" :: "n"(n))

// ===========================================================================
// convert fp32 -> fp16
// ===========================================================================
__global__ void conv_half(const float4* __restrict__ in,
                          uint2* __restrict__ out, int n4)
{
    int i = blockIdx.x * blockDim.x + threadIdx.x;
    if (i >= n4) return;
    float4 v = in[i];
    out[i] = make_uint2(packh2(v.x, v.y), packh2(v.z, v.w));
}

// ===========================================================================
// fp16 GEMM: C[M,N] = A[M,K] @ W[N,K]^T + bias.  cp.async 4-stage pipeline.
// CTA tile 128x128, K-chunk 32. Stage 16KB: A (8KB) | W (8KB). occ 2.
// EPI==0: QKV epilogue (Q,K fp32; V fp16).  EPI==1: fp32 C.
// ===========================================================================
#define GSTG 16384
#define GK_SMEM (4*GSTG)

template<int EPI>
__global__ __launch_bounds__(256, 2) void gemm_f16(
    const __half* __restrict__ A, const __half* __restrict__ W,
    const float* __restrict__ bias, float* __restrict__ C, int N, int K)
{
    extern __shared__ char smc[];
    const uint32_t sb = smem_u32(smc);

    const int tid  = threadIdx.x;
    const int warp = tid >> 5, lane = tid & 31;
    const int wm = warp & 3, cg = warp >> 2;
    const int m0 = blockIdx.y * 128, n0 = blockIdx.x * 128;

    // 512 16B-chunks per array, 256 threads -> 2 chunks each
    const int rowA = tid >> 2, cA = tid & 3;
    const int rowB = (tid + 256) >> 2, cB = tid & 3;
    const uint32_t offA = swz(rowA, cA), offB = swz(rowB, cB);
    const __half* pA_A = A + (size_t)(m0 + rowA) * K + cA * 8;
    const __half* pW_A = W + (size_t)(n0 + rowA) * K + cA * 8;
    const __half* pA_B = A + (size_t)(m0 + rowB) * K + cB * 8;
    const __half* pW_B = W + (size_t)(n0 + rowB) * K + cB * 8;

    float acc[2][8][4];
    #pragma unroll
    for (int mt = 0; mt < 2; mt++)
        #pragma unroll
        for (int nt = 0; nt < 8; nt++)
            #pragma unroll
            for (int i = 0; i < 4; i++) acc[mt][nt][i] = 0.f;

    uint32_t aOff[2][2], bOff[2][4];
    #pragma unroll
    for (int h = 0; h < 2; h++) {
        #pragma unroll
        for (int mt = 0; mt < 2; mt++) {
            int r = wm * 32 + mt * 16 + (lane & 15);
            int c = h * 2 + ((lane >> 4) & 1);
            aOff[h][mt] = swz(r, c);
        }
        #pragma unroll
        for (int ntp = 0; ntp < 4; ntp++) {
            int r = cg * 64 + ntp * 16 + (lane & 7) + ((lane >> 4) & 1) * 8;
            int c = h * 2 + ((lane >> 3) & 1);
            bOff[h][ntp] = swz(r, c);
        }
    }

    const int NSTG = K / 32;

    auto issue = [&](int s) {
        const uint32_t base = sb + (s & 3) * GSTG;
        const int k0 = s * 32;
        cpa16(base + offA,        pA_A + k0);
        cpa16(base + 8192 + offA, pW_A + k0);
        cpa16(base + offB,        pA_B + k0);
        cpa16(base + 8192 + offB, pW_B + k0);
    };

    issue(0); CP_COMMIT();
    issue(1); CP_COMMIT();
    issue(2); CP_COMMIT();

    for (int s = 0; s < NSTG; s++) {
        CP_WAIT(2);
        __syncthreads();
        if (s + 3 < NSTG) issue(s + 3);
        CP_COMMIT();

        const uint32_t base = sb + (s & 3) * GSTG;
        #pragma unroll
        for (int h = 0; h < 2; h++) {
            uint32_t a0[4], a1[4];
            ldmx4(base + aOff[h][0], a0);
            ldmx4(base + aOff[h][1], a1);
            #pragma unroll
            for (int ntp = 0; ntp < 4; ntp++) {
                uint32_t bfr[4];
                ldmx4(base + 8192 + bOff[h][ntp], bfr);
                mma16816(acc[0][2*ntp],   a0, bfr[0], bfr[1]);
                mma16816(acc[0][2*ntp+1], a0, bfr[2], bfr[3]);
                mma16816(acc[1][2*ntp],   a1, bfr[0], bfr[1]);
                mma16816(acc[1][2*ntp+1], a1, bfr[2], bfr[3]);
            }
        }
    }

    // ---------------- epilogue ---------------------------------------------
    const int g = lane >> 2, tig = lane & 3;
    const int nBase = n0 + cg * 64;

    float bcol[8][2];
    #pragma unroll
    for (int nt = 0; nt < 8; nt++) {
        bcol[nt][0] = bias[nBase + nt * 8 + tig * 2];
        bcol[nt][1] = bias[nBase + nt * 8 + tig * 2 + 1];
    }

    if (EPI == 0) {
        int part = nBase >> 10;
        int hd   = (nBase & 1023) >> 6;
        #pragma unroll
        for (int mt = 0; mt < 2; mt++)
            #pragma unroll
            for (int half = 0; half < 2; half++) {
                int m = m0 + wm * 32 + mt * 16 + g + half * 8;
                int b = m >> 11, sq = m & 2047;
                size_t rb = (((size_t)b * NH + hd) * NS + sq) * NDH;
                if (part < 2) {
                    float* dst = part ? g_K : g_Q;
                    #pragma unroll
                    for (int nt = 0; nt < 8; nt++) {
                        int d = nt * 8 + tig * 2;
                        float2 v;
                        v.x = acc[mt][nt][half*2]   + bcol[nt][0];
                        v.y = acc[mt][nt][half*2+1] + bcol[nt][1];
                        *(float2*)(dst + rb + d) = v;
                    }
                } else {
                    #pragma unroll
                    for (int nt = 0; nt < 8; nt++) {
                        int d = nt * 8 + tig * 2;
                        float vx = acc[mt][nt][half*2]   + bcol[nt][0];
                        float vy = acc[mt][nt][half*2+1] + bcol[nt][1];
                        *(uint32_t*)((char*)g_Vhf + (rb + d) * 2) = packh2(vx, vy);
                    }
                }
            }
    } else {
        #pragma unroll
        for (int mt = 0; mt < 2; mt++)
            #pragma unroll
            for (int half = 0; half < 2; half++) {
                int m = m0 + wm * 32 + mt * 16 + g + half * 8;
                #pragma unroll
                for (int nt = 0; nt < 8; nt++) {
                    int n = nBase + nt * 8 + tig * 2;
                    float2 v;
                    v.x = acc[mt][nt][half*2]   + bcol[nt][0];
                    v.y = acc[mt][nt][half*2+1] + bcol[nt][1];
                    *(float2*)(C + (size_t)m * N + n) = v;
                }
            }
    }
}

// ===========================================================================
// RoPE: read fp32 Q/K, rotate, write fp16 (Q pre-scaled by 0.125).
// ===========================================================================
__global__ void rope_half(const int* __restrict__ p)
{
    int idx = blockIdx.x * blockDim.x + threadIdx.x;
    if (idx >= NB*NH*NS*32) return;
    int i = idx & 31;
    int t = idx >> 5;
    int s = t & (NS - 1);
    int b = t >> 15;
    int pos = p[b * NS + s];

    float f = (float)exp(-(double)i * (9.210340371976184 / 32.0));
    float ang = (float)pos * f;
    float c, sn;
    sincosf(ang, &sn, &c);

    size_t base = (size_t)t * NDH;
    float q1 = g_Q[base + i], q2 = g_Q[base + i + 32];
    float k1 = g_K[base + i], k2 = g_K[base + i + 32];
    g_Qhf[base + i]      = __float2half_rn((q1 * c + q2 * sn) * 0.125f);
    g_Qhf[base + i + 32] = __float2half_rn((q2 * c - q1 * sn) * 0.125f);
    g_Khf[base + i]      = __float2half_rn(k1 * c + k2 * sn);
    g_Khf[base + i + 32] = __float2half_rn(k2 * c - k1 * sn);
}

// ===========================================================================
// fp16 tensor-core flash attention. 128 threads / 4 warps, 128 q per CTA,
// warp owns 32 q (mt=2). cp.async double-buffered K/V stages.
// smem: Q 16KB | 2 stages @16KB (K 8KB | V 8KB) = 48KB total.
// ===========================================================================
#define AQ 0
#define ASTG_BASE 16384
#define ASTG 16384
#define AT_SMEM (ASTG_BASE + 2*ASTG)    // 49152

__global__ __launch_bounds__(128, 3) void attn_f16()
{
    extern __shared__ char sma[];
    const uint32_t sb = smem_u32(sma);

    const int tid = threadIdx.x;
    const int warp = tid >> 5, lane = tid & 31;
    const int qt = blockIdx.x, bh = blockIdx.y;

    const size_t qbase  = ((size_t)bh * NS + qt * 128) * NDH;
    const size_t kvbase = (size_t)bh * NS * NDH;

    // ---- Q fill: 128 rows x 8 chunks = 1024, 128 threads x 8 --------------
    {
        #pragma unroll
        for (int j = 0; j < 8; j++) {
            int idx = tid + j * 128;
            int row = idx >> 3, c = idx & 7;
            cpa16(sb + AQ + swz128(row, c), g_Qhf + qbase + (size_t)row * NDH + c * 8);
        }
        CP_COMMIT();
    }

    // K/V stage: K 512 chunks + V 512, 128 threads -> 8 each
    const int rKV = tid >> 3, cKV = tid & 7;     // rows 0..15 base
    auto issue_kv = [&](int kt) {
        const uint32_t base = sb + ASTG_BASE + (kt & 1) * ASTG;
        #pragma unroll
        for (int j = 0; j < 4; j++) {
            int row = rKV + j * 16;
            uint32_t o = swz128(row, cKV);
            size_t go = kvbase + (size_t)(kt * 64 + row) * NDH + cKV * 8;
            cpa16(base + o,        g_Khf + go);
            cpa16(base + 8192 + o, g_Vhf + go);
        }
    };
    issue_kv(0); CP_COMMIT();

    // ---- fragment smem offsets --------------------------------------------
    uint32_t qOff[4][2];
    #pragma unroll
    for (int kc = 0; kc < 4; kc++)
        #pragma unroll
        for (int mt = 0; mt < 2; mt++) {
            int r = warp * 32 + mt * 16 + (lane & 15);
            int c = kc * 2 + ((lane >> 4) & 1);
            qOff[kc][mt] = swz128(r, c);
        }
    uint32_t kOff[4][4];
    #pragma unroll
    for (int kc = 0; kc < 4; kc++)
        #pragma unroll
        for (int ntp = 0; ntp < 4; ntp++) {
            int r = ntp * 16 + (lane & 7) + ((lane >> 4) & 1) * 8;
            int c = kc * 2 + ((lane >> 3) & 1);
            kOff[kc][ntp] = swz128(r, c);
        }
    uint32_t vOff[4][4];
    #pragma unroll
    for (int kq = 0; kq < 4; kq++)
        #pragma unroll
        for (int dp = 0; dp < 4; dp++) {
            int r = kq * 16 + (lane & 7) + ((lane >> 3) & 1) * 8;
            int c = dp * 2 + ((lane >> 4) & 1);
            vOff[kq][dp] = swz128(r, c);
        }

    float Oa[2][8][4];
    float mrun[2][2], lrun[2][2];
    #pragma unroll
    for (int mt = 0; mt < 2; mt++) {
        mrun[mt][0] = -INFINITY; mrun[mt][1] = -INFINITY;
        lrun[mt][0] = 0.f;       lrun[mt][1] = 0.f;
        #pragma unroll
        for (int dt = 0; dt < 8; dt++)
            #pragma unroll
            for (int i = 0; i < 4; i++) Oa[mt][dt][i] = 0.f;
    }

    for (int kt = 0; kt < NS / 64; kt++) {
        CP_WAIT(0);
        __syncthreads();
        if (kt + 1 < NS / 64) issue_kv(kt + 1);
        CP_COMMIT();

        const uint32_t kb = sb + ASTG_BASE + (kt & 1) * ASTG;

        // ---- S = Q K^T ----------------------------------------------------
        float S[2][8][4];
        #pragma unroll
        for (int mt = 0; mt < 2; mt++)
            #pragma unroll
            for (int nt = 0; nt < 8; nt++)
                #pragma unroll
                for (int i = 0; i < 4; i++) S[mt][nt][i] = 0.f;

        #pragma unroll
        for (int kc = 0; kc < 4; kc++) {
            uint32_t q0[4], q1[4];
            ldmx4(sb + AQ + qOff[kc][0], q0);
            ldmx4(sb + AQ + qOff[kc][1], q1);
            #pragma unroll
            for (int ntp = 0; ntp < 4; ntp++) {
                uint32_t kf[4];
                ldmx4(kb + kOff[kc][ntp], kf);
                mma16816(S[0][2*ntp],   q0, kf[0], kf[1]);
                mma16816(S[0][2*ntp+1], q0, kf[2], kf[3]);
                mma16816(S[1][2*ntp],   q1, kf[0], kf[1]);
                mma16816(S[1][2*ntp+1], q1, kf[2], kf[3]);
            }
        }

        // ---- online softmax -----------------------------------------------
        #pragma unroll
        for (int mt = 0; mt < 2; mt++) {
            float mx0 = -INFINITY, mx1 = -INFINITY;
            #pragma unroll
            for (int j = 0; j < 8; j++) {
                mx0 = fmaxf(mx0, fmaxf(S[mt][j][0], S[mt][j][1]));
                mx1 = fmaxf(mx1, fmaxf(S[mt][j][2], S[mt][j][3]));
            }
            mx0 = fmaxf(mx0, __shfl_xor_sync(0xffffffffu, mx0, 1));
            mx0 = fmaxf(mx0, __shfl_xor_sync(0xffffffffu, mx0, 2));
            mx1 = fmaxf(mx1, __shfl_xor_sync(0xffffffffu, mx1, 1));
            mx1 = fmaxf(mx1, __shfl_xor_sync(0xffffffffu, mx1, 2));
            float nm0 = fmaxf(mrun[mt][0], mx0);
            float nm1 = fmaxf(mrun[mt][1], mx1);
            float a0 = __expf(mrun[mt][0] - nm0);
            float a1 = __expf(mrun[mt][1] - nm1);
            mrun[mt][0] = nm0; mrun[mt][1] = nm1;
            float s0 = 0.f, s1 = 0.f;
            #pragma unroll
            for (int j = 0; j < 8; j++) {
                S[mt][j][0] = __expf(S[mt][j][0] - nm0); s0 += S[mt][j][0];
                S[mt][j][1] = __expf(S[mt][j][1] - nm0); s0 += S[mt][j][1];
                S[mt][j][2] = __expf(S[mt][j][2] - nm1); s1 += S[mt][j][2];
                S[mt][j][3] = __expf(S[mt][j][3] - nm1); s1 += S[mt][j][3];
            }
            s0 += __shfl_xor_sync(0xffffffffu, s0, 1);
            s0 += __shfl_xor_sync(0xffffffffu, s0, 2);
            s1 += __shfl_xor_sync(0xffffffffu, s1, 1);
            s1 += __shfl_xor_sync(0xffffffffu, s1, 2);
            lrun[mt][0] = lrun[mt][0] * a0 + s0;
            lrun[mt][1] = lrun[mt][1] * a1 + s1;
            #pragma unroll
            for (int dt = 0; dt < 8; dt++) {
                Oa[mt][dt][0] *= a0; Oa[mt][dt][1] *= a0;
                Oa[mt][dt][2] *= a1; Oa[mt][dt][3] *= a1;
            }
        }

        // ---- O += P V -----------------------------------------------------
        #pragma unroll
        for (int kq = 0; kq < 4; kq++) {
            uint32_t pa[2][4];
            #pragma unroll
            for (int mt = 0; mt < 2; mt++) {
                pa[mt][0] = packh2(S[mt][2*kq][0],   S[mt][2*kq][1]);
                pa[mt][1] = packh2(S[mt][2*kq][2],   S[mt][2*kq][3]);
                pa[mt][2] = packh2(S[mt][2*kq+1][0], S[mt][2*kq+1][1]);
                pa[mt][3] = packh2(S[mt][2*kq+1][2], S[mt][2*kq+1][3]);
            }
            #pragma unroll
            for (int dp = 0; dp < 4; dp++) {
                uint32_t vf[4];
                ldmx4t(kb + 8192 + vOff[kq][dp], vf);
                mma16816(Oa[0][2*dp],   pa[0], vf[0], vf[1]);
                mma16816(Oa[0][2*dp+1], pa[0], vf[2], vf[3]);
                mma16816(Oa[1][2*dp],   pa[1], vf[0], vf[1]);
                mma16816(Oa[1][2*dp+1], pa[1], vf[2], vf[3]);
            }
        }
    }

    // ---- epilogue: O /= l -> ctx fp16 [B,S,H*Dh] --------------------------
    const int b = bh >> 4, h = bh & 15;
    const int g = lane >> 2, tg = lane & 3;
    #pragma unroll
    for (int mt = 0; mt < 2; mt++)
        #pragma unroll
        for (int half = 0; half < 2; half++) {
            int q = qt * 128 + warp * 32 + mt * 16 + g + half * 8;
            float inv = 1.0f / lrun[mt][half];
            size_t rb = ((size_t)b * NS + q) * ND + h * NDH;
            #pragma unroll
            for (int dt = 0; dt < 8; dt++) {
                float vx = Oa[mt][dt][half*2]   * inv;
                float vy = Oa[mt][dt][half*2+1] * inv;
                size_t o = rb + dt * 8 + tg * 2;
                *(uint32_t*)((char*)g_ctxhf + o * 2) = packh2(vx, vy);
            }
        }
}

// ===========================================================================
extern "C" void kernel_launch(void* const* d_in, const int* in_sizes, int n_in,
                              void* d_out, int out_size)
{
    (void)in_sizes; (void)n_in; (void)out_size;
    const float* x      = (const float*)d_in[0];
    const int*   p      = (const int*)d_in[1];
    const float* Wqkv_w = (const float*)d_in[2];
    const float* Wqkv_b = (const float*)d_in[3];
    const float* Wo_w   = (const float*)d_in[4];
    const float* Wo_b   = (const float*)d_in[5];
    float* out = (float*)d_out;

    cudaFuncSetAttribute(gemm_f16<0>,
                         cudaFuncAttributeMaxDynamicSharedMemorySize, GK_SMEM);
    cudaFuncSetAttribute(gemm_f16<1>,
                         cudaFuncAttributeMaxDynamicSharedMemorySize, GK_SMEM);
    cudaFuncSetAttribute(attn_f16,
                         cudaFuncAttributeMaxDynamicSharedMemorySize, AT_SMEM);

    __half *xh, *wqh, *woh, *ctxh;
    cudaGetSymbolAddress((void**)&xh,   g_xhf);
    cudaGetSymbolAddress((void**)&wqh,  g_wqhf);
    cudaGetSymbolAddress((void**)&woh,  g_wohf);
    cudaGetSymbolAddress((void**)&ctxh, g_ctxhf);

    int n4x = MT * ND / 4, n4wq = 3 * ND * ND / 4, n4wo = ND * ND / 4;
    conv_half<<<(n4x  + 255) / 256, 256>>>((const float4*)x,      (uint2*)xh,  n4x);
    conv_half<<<(n4wq + 255) / 256, 256>>>((const float4*)Wqkv_w, (uint2*)wqh, n4wq);
    conv_half<<<(n4wo + 255) / 256, 256>>>((const float4*)Wo_w,   (uint2*)woh, n4wo);

    dim3 g1(3 * ND / 128, MT / 128);
    gemm_f16<0><<<g1, 256, GK_SMEM>>>(xh, wqh, Wqkv_b, nullptr, 3 * ND, ND);

    int nrope = NB * NH * NS * 32;
    rope_half<<<(nrope + 255) / 256, 256>>>(p);

    attn_f16<<<dim3(NS / 128, NB * NH), 128, AT_SMEM>>>();

    dim3 g2(ND / 128, MT / 128);
    gemm_f16<1><<<g2, 256, GK_SMEM>>>(ctxh, woh, Wo_b, out, ND, ND);
}

// round 9
// speedup vs baseline: 2.7574x; 1.3396x over previous
#include <cuda_runtime.h>
#include <cuda_fp16.h>
#include <math.h>
#include <stdint.h>

#define NB   4
#define NS   2048
#define ND   1024
#define NH   16
#define NDH  64
#define MT   (NB*NS)          // 8192 rows
#define QKV_ELEMS ((size_t)NB*NH*NS*NDH)

// ---------------- scratch (device globals: no allocation allowed) ----------
__device__ __half g_Qhf[QKV_ELEMS];           // post-RoPE, *0.125, fp16
__device__ __half g_Khf[QKV_ELEMS];
__device__ __half g_Vhf[QKV_ELEMS];
__device__ __half g_xhf[(size_t)MT*ND];
__device__ __half g_wqhf[(size_t)3*ND*ND];
__device__ __half g_wohf[(size_t)ND*ND];
__device__ __half g_ctxhf[(size_t)MT*ND];
__device__ float  g_freq[32];                 // 10000^(-i/32), fp32 (from double)

// ======================= helpers ===========================================
__device__ __forceinline__ uint32_t smem_u32(const void* p) {
    uint32_t a;
    asm("{ .reg .u64 t; cvta.to.shared.u64 t, %1; cvt.u32.u64 %0, t; }"
        : "=r"(a) : "l"(p));
    return a;
}
__device__ __forceinline__ void ldmx4(uint32_t addr, uint32_t r[4]) {
    asm volatile("ldmatrix.sync.aligned.m8n8.x4.shared.b16 {%0,%1,%2,%3}, [%4];"
                 : "=r"(r[0]), "=r"(r[1]), "=r"(r[2]), "=r"(r[3]) : "r"(addr));
}
__device__ __forceinline__ void ldmx4t(uint32_t addr, uint32_t r[4]) {
    asm volatile("ldmatrix.sync.aligned.m8n8.x4.trans.shared.b16 {%0,%1,%2,%3}, [%4];"
                 : "=r"(r[0]), "=r"(r[1]), "=r"(r[2]), "=r"(r[3]) : "r"(addr));
}
__device__ __forceinline__ void mma16816(float c[4], const uint32_t a[4],
                                         uint32_t b0, uint32_t b1) {
    asm("mma.sync.aligned.m16n8k16.row.col.f32.f16.f16.f32 "
        "{%0,%1,%2,%3}, {%4,%5,%6,%7}, {%8,%9}, {%0,%1,%2,%3};"
        : "+f"(c[0]), "+f"(c[1]), "+f"(c[2]), "+f"(c[3])
        : "r"(a[0]), "r"(a[1]), "r"(a[2]), "r"(a[3]), "r"(b0), "r"(b1));
}
__device__ __forceinline__ uint32_t packh2(float x, float y) {
    __half2 h = __floats2half2_rn(x, y);
    return *(uint32_t*)&h;
}
// XOR swizzle: 16B chunk c of 64B row
__device__ __forceinline__ uint32_t swz(int row, int c) {
    return (uint32_t)(row * 64 + ((c ^ ((row >> 1) & 3)) * 16));
}
// XOR swizzle for 128B rows
__device__ __forceinline__ uint32_t swz128(int row, int c) {
    return (uint32_t)(row * 128 + ((c ^ (row & 7)) * 16));
}
__device__ __forceinline__ void cpa16(uint32_t dst, const void* src) {
    asm volatile("cp.async.cg.shared.global [%0], [%1], 16;"
                 :: "r"(dst), "l"(src));
}
#define CP_COMMIT()  asm volatile("cp.async.commit_group;")
#define CP_WAIT(n)   asm volatile("cp.async.wait_group %0;" :: "n"(n))

// ===========================================================================
// setup: RoPE freqs (double-precision exp, matching jnp fp32-rounded values)
// ===========================================================================
__global__ void freq_kernel()
{
    int i = threadIdx.x;
    if (i < 32)
        g_freq[i] = (float)exp(-(double)i * (9.210340371976184 / 32.0));
}

// ===========================================================================
// merged fp32 -> fp16 converts for x, Wqkv, Wo
// ===========================================================================
__global__ void conv_all(const float4* __restrict__ x,
                         const float4* __restrict__ wq,
                         const float4* __restrict__ wo,
                         uint2* __restrict__ xh, uint2* __restrict__ wqh,
                         uint2* __restrict__ woh,
                         int n4x, int n4wq, int n4wo)
{
    int i = blockIdx.x * blockDim.x + threadIdx.x;
    const float4* src; uint2* dst; int idx;
    if (i < n4x)                 { src = x;  dst = xh;  idx = i; }
    else if (i < n4x + n4wq)     { src = wq; dst = wqh; idx = i - n4x; }
    else if (i < n4x + n4wq + n4wo) { src = wo; dst = woh; idx = i - n4x - n4wq; }
    else return;
    float4 v = src[idx];
    dst[idx] = make_uint2(packh2(v.x, v.y), packh2(v.z, v.w));
}

// ===========================================================================
// fp16 GEMM: C[M,N] = A[M,K] @ W[N,K]^T + bias.  cp.async 4-stage pipeline.
// EPI==0: fused QKV epilogue — RoPE(Q,K) -> fp16 (Q *0.125), V -> fp16.
// EPI==1: fp32 C.
// ===========================================================================
#define GSTG 16384
#define GK_SMEM (4*GSTG)

template<int EPI>
__global__ __launch_bounds__(256, 2) void gemm_f16(
    const __half* __restrict__ A, const __half* __restrict__ W,
    const float* __restrict__ bias, const int* __restrict__ posp,
    float* __restrict__ C, int N, int K)
{
    extern __shared__ char smc[];
    const uint32_t sb = smem_u32(smc);

    const int tid  = threadIdx.x;
    const int warp = tid >> 5, lane = tid & 31;
    const int wm = warp & 3, cg = warp >> 2;
    const int m0 = blockIdx.y * 128, n0 = blockIdx.x * 128;

    const int rowA = tid >> 2, cA = tid & 3;
    const int rowB = (tid + 256) >> 2, cB = tid & 3;
    const uint32_t offA = swz(rowA, cA), offB = swz(rowB, cB);
    const __half* pA_A = A + (size_t)(m0 + rowA) * K + cA * 8;
    const __half* pW_A = W + (size_t)(n0 + rowA) * K + cA * 8;
    const __half* pA_B = A + (size_t)(m0 + rowB) * K + cB * 8;
    const __half* pW_B = W + (size_t)(n0 + rowB) * K + cB * 8;

    float acc[2][8][4];
    #pragma unroll
    for (int mt = 0; mt < 2; mt++)
        #pragma unroll
        for (int nt = 0; nt < 8; nt++)
            #pragma unroll
            for (int i = 0; i < 4; i++) acc[mt][nt][i] = 0.f;

    uint32_t aOff[2][2], bOff[2][4];
    #pragma unroll
    for (int h = 0; h < 2; h++) {
        #pragma unroll
        for (int mt = 0; mt < 2; mt++) {
            int r = wm * 32 + mt * 16 + (lane & 15);
            int c = h * 2 + ((lane >> 4) & 1);
            aOff[h][mt] = swz(r, c);
        }
        #pragma unroll
        for (int ntp = 0; ntp < 4; ntp++) {
            int r = cg * 64 + ntp * 16 + (lane & 7) + ((lane >> 4) & 1) * 8;
            int c = h * 2 + ((lane >> 3) & 1);
            bOff[h][ntp] = swz(r, c);
        }
    }

    const int NSTG = K / 32;

    auto issue = [&](int s) {
        const uint32_t base = sb + (s & 3) * GSTG;
        const int k0 = s * 32;
        cpa16(base + offA,        pA_A + k0);
        cpa16(base + 8192 + offA, pW_A + k0);
        cpa16(base + offB,        pA_B + k0);
        cpa16(base + 8192 + offB, pW_B + k0);
    };

    issue(0); CP_COMMIT();
    issue(1); CP_COMMIT();
    issue(2); CP_COMMIT();

    for (int s = 0; s < NSTG; s++) {
        CP_WAIT(2);
        __syncthreads();
        if (s + 3 < NSTG) issue(s + 3);
        CP_COMMIT();

        const uint32_t base = sb + (s & 3) * GSTG;
        #pragma unroll
        for (int h = 0; h < 2; h++) {
            uint32_t a0[4], a1[4];
            ldmx4(base + aOff[h][0], a0);
            ldmx4(base + aOff[h][1], a1);
            #pragma unroll
            for (int ntp = 0; ntp < 4; ntp++) {
                uint32_t bfr[4];
                ldmx4(base + 8192 + bOff[h][ntp], bfr);
                mma16816(acc[0][2*ntp],   a0, bfr[0], bfr[1]);
                mma16816(acc[0][2*ntp+1], a0, bfr[2], bfr[3]);
                mma16816(acc[1][2*ntp],   a1, bfr[0], bfr[1]);
                mma16816(acc[1][2*ntp+1], a1, bfr[2], bfr[3]);
            }
        }
    }

    // ---------------- epilogue ---------------------------------------------
    const int g = lane >> 2, tig = lane & 3;
    const int nBase = n0 + cg * 64;

    float bcol[8][2];
    #pragma unroll
    for (int nt = 0; nt < 8; nt++) {
        bcol[nt][0] = bias[nBase + nt * 8 + tig * 2];
        bcol[nt][1] = bias[nBase + nt * 8 + tig * 2 + 1];
    }

    if (EPI == 0) {
        int part = nBase >> 10;
        int hd   = (nBase & 1023) >> 6;
        if (part < 2) {
            // ---- fused RoPE: rotate pairs (d, d+32) = (nt, nt+4), write fp16
            __half* dst = part ? g_Khf : g_Qhf;
            const float sc = part ? 1.0f : 0.125f;
            float fr[4][2];
            #pragma unroll
            for (int nt = 0; nt < 4; nt++) {
                fr[nt][0] = g_freq[nt * 8 + tig * 2];
                fr[nt][1] = g_freq[nt * 8 + tig * 2 + 1];
            }
            #pragma unroll
            for (int mt = 0; mt < 2; mt++)
                #pragma unroll
                for (int half = 0; half < 2; half++) {
                    int m = m0 + wm * 32 + mt * 16 + g + half * 8;
                    int b = m >> 11, sq = m & 2047;
                    size_t rb = (((size_t)b * NH + hd) * NS + sq) * NDH;
                    float pos = (float)posp[b * NS + sq];
                    #pragma unroll
                    for (int nt = 0; nt < 4; nt++) {
                        float r1[2], r2[2];
                        #pragma unroll
                        for (int k = 0; k < 2; k++) {
                            float ang = pos * fr[nt][k];
                            float c, sn;
                            sincosf(ang, &sn, &c);
                            float q1 = acc[mt][nt][half*2 + k]   + bcol[nt][k];
                            float q2 = acc[mt][nt+4][half*2 + k] + bcol[nt+4][k];
                            r1[k] = (q1 * c + q2 * sn) * sc;
                            r2[k] = (q2 * c - q1 * sn) * sc;
                        }
                        int d = nt * 8 + tig * 2;
                        *(uint32_t*)((char*)dst + (rb + d) * 2)      = packh2(r1[0], r1[1]);
                        *(uint32_t*)((char*)dst + (rb + d + 32) * 2) = packh2(r2[0], r2[1]);
                    }
                }
        } else {
            // ---- V: bias + fp16 store
            #pragma unroll
            for (int mt = 0; mt < 2; mt++)
                #pragma unroll
                for (int half = 0; half < 2; half++) {
                    int m = m0 + wm * 32 + mt * 16 + g + half * 8;
                    int b = m >> 11, sq = m & 2047;
                    size_t rb = (((size_t)b * NH + hd) * NS + sq) * NDH;
                    #pragma unroll
                    for (int nt = 0; nt < 8; nt++) {
                        int d = nt * 8 + tig * 2;
                        float vx = acc[mt][nt][half*2]   + bcol[nt][0];
                        float vy = acc[mt][nt][half*2+1] + bcol[nt][1];
                        *(uint32_t*)((char*)g_Vhf + (rb + d) * 2) = packh2(vx, vy);
                    }
                }
        }
    } else {
        #pragma unroll
        for (int mt = 0; mt < 2; mt++)
            #pragma unroll
            for (int half = 0; half < 2; half++) {
                int m = m0 + wm * 32 + mt * 16 + g + half * 8;
                #pragma unroll
                for (int nt = 0; nt < 8; nt++) {
                    int n = nBase + nt * 8 + tig * 2;
                    float2 v;
                    v.x = acc[mt][nt][half*2]   + bcol[nt][0];
                    v.y = acc[mt][nt][half*2+1] + bcol[nt][1];
                    *(float2*)(C + (size_t)m * N + n) = v;
                }
            }
    }
}

// ===========================================================================
// fp16 tensor-core flash attention (unchanged from passing R8 version).
// ===========================================================================
#define AQ 0
#define ASTG_BASE 16384
#define ASTG 16384
#define AT_SMEM (ASTG_BASE + 2*ASTG)    // 49152

__global__ __launch_bounds__(128, 3) void attn_f16()
{
    extern __shared__ char sma[];
    const uint32_t sb = smem_u32(sma);

    const int tid = threadIdx.x;
    const int warp = tid >> 5, lane = tid & 31;
    const int qt = blockIdx.x, bh = blockIdx.y;

    const size_t qbase  = ((size_t)bh * NS + qt * 128) * NDH;
    const size_t kvbase = (size_t)bh * NS * NDH;

    {
        #pragma unroll
        for (int j = 0; j < 8; j++) {
            int idx = tid + j * 128;
            int row = idx >> 3, c = idx & 7;
            cpa16(sb + AQ + swz128(row, c), g_Qhf + qbase + (size_t)row * NDH + c * 8);
        }
        CP_COMMIT();
    }

    const int rKV = tid >> 3, cKV = tid & 7;
    auto issue_kv = [&](int kt) {
        const uint32_t base = sb + ASTG_BASE + (kt & 1) * ASTG;
        #pragma unroll
        for (int j = 0; j < 4; j++) {
            int row = rKV + j * 16;
            uint32_t o = swz128(row, cKV);
            size_t go = kvbase + (size_t)(kt * 64 + row) * NDH + cKV * 8;
            cpa16(base + o,        g_Khf + go);
            cpa16(base + 8192 + o, g_Vhf + go);
        }
    };
    issue_kv(0); CP_COMMIT();

    uint32_t qOff[4][2];
    #pragma unroll
    for (int kc = 0; kc < 4; kc++)
        #pragma unroll
        for (int mt = 0; mt < 2; mt++) {
            int r = warp * 32 + mt * 16 + (lane & 15);
            int c = kc * 2 + ((lane >> 4) & 1);
            qOff[kc][mt] = swz128(r, c);
        }
    uint32_t kOff[4][4];
    #pragma unroll
    for (int kc = 0; kc < 4; kc++)
        #pragma unroll
        for (int ntp = 0; ntp < 4; ntp++) {
            int r = ntp * 16 + (lane & 7) + ((lane >> 4) & 1) * 8;
            int c = kc * 2 + ((lane >> 3) & 1);
            kOff[kc][ntp] = swz128(r, c);
        }
    uint32_t vOff[4][4];
    #pragma unroll
    for (int kq = 0; kq < 4; kq++)
        #pragma unroll
        for (int dp = 0; dp < 4; dp++) {
            int r = kq * 16 + (lane & 7) + ((lane >> 3) & 1) * 8;
            int c = dp * 2 + ((lane >> 4) & 1);
            vOff[kq][dp] = swz128(r, c);
        }

    float Oa[2][8][4];
    float mrun[2][2], lrun[2][2];
    #pragma unroll
    for (int mt = 0; mt < 2; mt++) {
        mrun[mt][0] = -INFINITY; mrun[mt][1] = -INFINITY;
        lrun[mt][0] = 0.f;       lrun[mt][1] = 0.f;
        #pragma unroll
        for (int dt = 0; dt < 8; dt++)
            #pragma unroll
            for (int i = 0; i < 4; i++) Oa[mt][dt][i] = 0.f;
    }

    for (int kt = 0; kt < NS / 64; kt++) {
        CP_WAIT(0);
        __syncthreads();
        if (kt + 1 < NS / 64) issue_kv(kt + 1);
        CP_COMMIT();

        const uint32_t kb = sb + ASTG_BASE + (kt & 1) * ASTG;

        float S[2][8][4];
        #pragma unroll
        for (int mt = 0; mt < 2; mt++)
            #pragma unroll
            for (int nt = 0; nt < 8; nt++)
                #pragma unroll
                for (int i = 0; i < 4; i++) S[mt][nt][i] = 0.f;

        #pragma unroll
        for (int kc = 0; kc < 4; kc++) {
            uint32_t q0[4], q1[4];
            ldmx4(sb + AQ + qOff[kc][0], q0);
            ldmx4(sb + AQ + qOff[kc][1], q1);
            #pragma unroll
            for (int ntp = 0; ntp < 4; ntp++) {
                uint32_t kf[4];
                ldmx4(kb + kOff[kc][ntp], kf);
                mma16816(S[0][2*ntp],   q0, kf[0], kf[1]);
                mma16816(S[0][2*ntp+1], q0, kf[2], kf[3]);
                mma16816(S[1][2*ntp],   q1, kf[0], kf[1]);
                mma16816(S[1][2*ntp+1], q1, kf[2], kf[3]);
            }
        }

        #pragma unroll
        for (int mt = 0; mt < 2; mt++) {
            float mx0 = -INFINITY, mx1 = -INFINITY;
            #pragma unroll
            for (int j = 0; j < 8; j++) {
                mx0 = fmaxf(mx0, fmaxf(S[mt][j][0], S[mt][j][1]));
                mx1 = fmaxf(mx1, fmaxf(S[mt][j][2], S[mt][j][3]));
            }
            mx0 = fmaxf(mx0, __shfl_xor_sync(0xffffffffu, mx0, 1));
            mx0 = fmaxf(mx0, __shfl_xor_sync(0xffffffffu, mx0, 2));
            mx1 = fmaxf(mx1, __shfl_xor_sync(0xffffffffu, mx1, 1));
            mx1 = fmaxf(mx1, __shfl_xor_sync(0xffffffffu, mx1, 2));
            float nm0 = fmaxf(mrun[mt][0], mx0);
            float nm1 = fmaxf(mrun[mt][1], mx1);
            float a0 = __expf(mrun[mt][0] - nm0);
            float a1 = __expf(mrun[mt][1] - nm1);
            mrun[mt][0] = nm0; mrun[mt][1] = nm1;
            float s0 = 0.f, s1 = 0.f;
            #pragma unroll
            for (int j = 0; j < 8; j++) {
                S[mt][j][0] = __expf(S[mt][j][0] - nm0); s0 += S[mt][j][0];
                S[mt][j][1] = __expf(S[mt][j][1] - nm0); s0 += S[mt][j][1];
                S[mt][j][2] = __expf(S[mt][j][2] - nm1); s1 += S[mt][j][2];
                S[mt][j][3] = __expf(S[mt][j][3] - nm1); s1 += S[mt][j][3];
            }
            s0 += __shfl_xor_sync(0xffffffffu, s0, 1);
            s0 += __shfl_xor_sync(0xffffffffu, s0, 2);
            s1 += __shfl_xor_sync(0xffffffffu, s1, 1);
            s1 += __shfl_xor_sync(0xffffffffu, s1, 2);
            lrun[mt][0] = lrun[mt][0] * a0 + s0;
            lrun[mt][1] = lrun[mt][1] * a1 + s1;
            #pragma unroll
            for (int dt = 0; dt < 8; dt++) {
                Oa[mt][dt][0] *= a0; Oa[mt][dt][1] *= a0;
                Oa[mt][dt][2] *= a1; Oa[mt][dt][3] *= a1;
            }
        }

        #pragma unroll
        for (int kq = 0; kq < 4; kq++) {
            uint32_t pa[2][4];
            #pragma unroll
            for (int mt = 0; mt < 2; mt++) {
                pa[mt][0] = packh2(S[mt][2*kq][0],   S[mt][2*kq][1]);
                pa[mt][1] = packh2(S[mt][2*kq][2],   S[mt][2*kq][3]);
                pa[mt][2] = packh2(S[mt][2*kq+1][0], S[mt][2*kq+1][1]);
                pa[mt][3] = packh2(S[mt][2*kq+1][2], S[mt][2*kq+1][3]);
            }
            #pragma unroll
            for (int dp = 0; dp < 4; dp++) {
                uint32_t vf[4];
                ldmx4t(kb + 8192 + vOff[kq][dp], vf);
                mma16816(Oa[0][2*dp],   pa[0], vf[0], vf[1]);
                mma16816(Oa[0][2*dp+1], pa[0], vf[2], vf[3]);
                mma16816(Oa[1][2*dp],   pa[1], vf[0], vf[1]);
                mma16816(Oa[1][2*dp+1], pa[1], vf[2], vf[3]);
            }
        }
    }

    const int b = bh >> 4, h = bh & 15;
    const int g = lane >> 2, tg = lane & 3;
    #pragma unroll
    for (int mt = 0; mt < 2; mt++)
        #pragma unroll
        for (int half = 0; half < 2; half++) {
            int q = qt * 128 + warp * 32 + mt * 16 + g + half * 8;
            float inv = 1.0f / lrun[mt][half];
            size_t rb = ((size_t)b * NS + q) * ND + h * NDH;
            #pragma unroll
            for (int dt = 0; dt < 8; dt++) {
                float vx = Oa[mt][dt][half*2]   * inv;
                float vy = Oa[mt][dt][half*2+1] * inv;
                size_t o = rb + dt * 8 + tg * 2;
                *(uint32_t*)((char*)g_ctxhf + o * 2) = packh2(vx, vy);
            }
        }
}

// ===========================================================================
extern "C" void kernel_launch(void* const* d_in, const int* in_sizes, int n_in,
                              void* d_out, int out_size)
{
    (void)in_sizes; (void)n_in; (void)out_size;
    const float* x      = (const float*)d_in[0];
    const int*   p      = (const int*)d_in[1];
    const float* Wqkv_w = (const float*)d_in[2];
    const float* Wqkv_b = (const float*)d_in[3];
    const float* Wo_w   = (const float*)d_in[4];
    const float* Wo_b   = (const float*)d_in[5];
    float* out = (float*)d_out;

    cudaFuncSetAttribute(gemm_f16<0>,
                         cudaFuncAttributeMaxDynamicSharedMemorySize, GK_SMEM);
    cudaFuncSetAttribute(gemm_f16<1>,
                         cudaFuncAttributeMaxDynamicSharedMemorySize, GK_SMEM);
    cudaFuncSetAttribute(attn_f16,
                         cudaFuncAttributeMaxDynamicSharedMemorySize, AT_SMEM);

    __half *xh, *wqh, *woh, *ctxh;
    cudaGetSymbolAddress((void**)&xh,   g_xhf);
    cudaGetSymbolAddress((void**)&wqh,  g_wqhf);
    cudaGetSymbolAddress((void**)&woh,  g_wohf);
    cudaGetSymbolAddress((void**)&ctxh, g_ctxhf);

    freq_kernel<<<1, 32>>>();

    int n4x = MT * ND / 4, n4wq = 3 * ND * ND / 4, n4wo = ND * ND / 4;
    int n4t = n4x + n4wq + n4wo;
    conv_all<<<(n4t + 255) / 256, 256>>>(
        (const float4*)x, (const float4*)Wqkv_w, (const float4*)Wo_w,
        (uint2*)xh, (uint2*)wqh, (uint2*)woh, n4x, n4wq, n4wo);

    dim3 g1(3 * ND / 128, MT / 128);
    gemm_f16<0><<<g1, 256, GK_SMEM>>>(xh, wqh, Wqkv_b, p, nullptr, 3 * ND, ND);

    attn_f16<<<dim3(NS / 128, NB * NH), 128, AT_SMEM>>>();

    dim3 g2(ND / 128, MT / 128);
    gemm_f16<1><<<g2, 256, GK_SMEM>>>(ctxh, woh, Wo_b, nullptr, out, ND, ND);
}

// round 10
// speedup vs baseline: 3.0104x; 1.0917x over previous
#include <cuda_runtime.h>
#include <cuda_fp16.h>
#include <math.h>
#include <stdint.h>

#define NB   4
#define NS   2048
#define ND   1024
#define NH   16
#define NDH  64
#define MT   (NB*NS)          // 8192 rows
#define QKV_ELEMS ((size_t)NB*NH*NS*NDH)
#define LOG2E 1.4426950408889634f

// ---------------- scratch (device globals: no allocation allowed) ----------
__device__ __half g_Qhf[QKV_ELEMS];           // post-RoPE, *0.125, fp16
__device__ __half g_Khf[QKV_ELEMS];
__device__ __half g_Vhf[QKV_ELEMS];
__device__ __half g_xhf[(size_t)MT*ND];
__device__ __half g_wqhf[(size_t)3*ND*ND];
__device__ __half g_wohf[(size_t)ND*ND];
__device__ __half g_ctxhf[(size_t)MT*ND];
__device__ float  g_freq[32];                 // 10000^(-i/32), fp32 (from double)

// ======================= helpers ===========================================
__device__ __forceinline__ uint32_t smem_u32(const void* p) {
    uint32_t a;
    asm("{ .reg .u64 t; cvta.to.shared.u64 t, %1; cvt.u32.u64 %0, t; }"
        : "=r"(a) : "l"(p));
    return a;
}
__device__ __forceinline__ void ldmx4(uint32_t addr, uint32_t r[4]) {
    asm volatile("ldmatrix.sync.aligned.m8n8.x4.shared.b16 {%0,%1,%2,%3}, [%4];"
                 : "=r"(r[0]), "=r"(r[1]), "=r"(r[2]), "=r"(r[3]) : "r"(addr));
}
__device__ __forceinline__ void ldmx4t(uint32_t addr, uint32_t r[4]) {
    asm volatile("ldmatrix.sync.aligned.m8n8.x4.trans.shared.b16 {%0,%1,%2,%3}, [%4];"
                 : "=r"(r[0]), "=r"(r[1]), "=r"(r[2]), "=r"(r[3]) : "r"(addr));
}
__device__ __forceinline__ void mma16816(float c[4], const uint32_t a[4],
                                         uint32_t b0, uint32_t b1) {
    asm("mma.sync.aligned.m16n8k16.row.col.f32.f16.f16.f32 "
        "{%0,%1,%2,%3}, {%4,%5,%6,%7}, {%8,%9}, {%0,%1,%2,%3};"
        : "+f"(c[0]), "+f"(c[1]), "+f"(c[2]), "+f"(c[3])
        : "r"(a[0]), "r"(a[1]), "r"(a[2]), "r"(a[3]), "r"(b0), "r"(b1));
}
__device__ __forceinline__ uint32_t packh2(float x, float y) {
    __half2 h = __floats2half2_rn(x, y);
    return *(uint32_t*)&h;
}
__device__ __forceinline__ uint32_t ex2h2(uint32_t x) {
    uint32_t d;
    asm("ex2.approx.f16x2 %0, %1;" : "=r"(d) : "r"(x));
    return d;
}
// XOR swizzle: 16B chunk c of 64B row
__device__ __forceinline__ uint32_t swz(int row, int c) {
    return (uint32_t)(row * 64 + ((c ^ ((row >> 1) & 3)) * 16));
}
// XOR swizzle for 128B rows
__device__ __forceinline__ uint32_t swz128(int row, int c) {
    return (uint32_t)(row * 128 + ((c ^ (row & 7)) * 16));
}
__device__ __forceinline__ void cpa16(uint32_t dst, const void* src) {
    asm volatile("cp.async.cg.shared.global [%0], [%1], 16;"
                 :: "r"(dst), "l"(src));
}
#define CP_COMMIT()  asm volatile("cp.async.commit_group;")
#define CP_WAIT(n)   asm volatile("cp.async.wait_group %0;" :: "n"(n))

// ===========================================================================
// setup: RoPE freqs (double-precision exp, matching jnp fp32-rounded values)
// ===========================================================================
__global__ void freq_kernel()
{
    int i = threadIdx.x;
    if (i < 32)
        g_freq[i] = (float)exp(-(double)i * (9.210340371976184 / 32.0));
}

// ===========================================================================
// merged fp32 -> fp16 converts for x, Wqkv, Wo
// ===========================================================================
__global__ void conv_all(const float4* __restrict__ x,
                         const float4* __restrict__ wq,
                         const float4* __restrict__ wo,
                         uint2* __restrict__ xh, uint2* __restrict__ wqh,
                         uint2* __restrict__ woh,
                         int n4x, int n4wq, int n4wo)
{
    int i = blockIdx.x * blockDim.x + threadIdx.x;
    const float4* src; uint2* dst; int idx;
    if (i < n4x)                 { src = x;  dst = xh;  idx = i; }
    else if (i < n4x + n4wq)     { src = wq; dst = wqh; idx = i - n4x; }
    else if (i < n4x + n4wq + n4wo) { src = wo; dst = woh; idx = i - n4x - n4wq; }
    else return;
    float4 v = src[idx];
    dst[idx] = make_uint2(packh2(v.x, v.y), packh2(v.z, v.w));
}

// ===========================================================================
// fp16 GEMM (unchanged from passing R9): cp.async 4-stage pipeline.
// EPI==0: fused QKV epilogue — RoPE(Q,K) -> fp16 (Q *0.125), V -> fp16.
// EPI==1: fp32 C.
// ===========================================================================
#define GSTG 16384
#define GK_SMEM (4*GSTG)

template<int EPI>
__global__ __launch_bounds__(256, 2) void gemm_f16(
    const __half* __restrict__ A, const __half* __restrict__ W,
    const float* __restrict__ bias, const int* __restrict__ posp,
    float* __restrict__ C, int N, int K)
{
    extern __shared__ char smc[];
    const uint32_t sb = smem_u32(smc);

    const int tid  = threadIdx.x;
    const int warp = tid >> 5, lane = tid & 31;
    const int wm = warp & 3, cg = warp >> 2;
    const int m0 = blockIdx.y * 128, n0 = blockIdx.x * 128;

    const int rowA = tid >> 2, cA = tid & 3;
    const int rowB = (tid + 256) >> 2, cB = tid & 3;
    const uint32_t offA = swz(rowA, cA), offB = swz(rowB, cB);
    const __half* pA_A = A + (size_t)(m0 + rowA) * K + cA * 8;
    const __half* pW_A = W + (size_t)(n0 + rowA) * K + cA * 8;
    const __half* pA_B = A + (size_t)(m0 + rowB) * K + cB * 8;
    const __half* pW_B = W + (size_t)(n0 + rowB) * K + cB * 8;

    float acc[2][8][4];
    #pragma unroll
    for (int mt = 0; mt < 2; mt++)
        #pragma unroll
        for (int nt = 0; nt < 8; nt++)
            #pragma unroll
            for (int i = 0; i < 4; i++) acc[mt][nt][i] = 0.f;

    uint32_t aOff[2][2], bOff[2][4];
    #pragma unroll
    for (int h = 0; h < 2; h++) {
        #pragma unroll
        for (int mt = 0; mt < 2; mt++) {
            int r = wm * 32 + mt * 16 + (lane & 15);
            int c = h * 2 + ((lane >> 4) & 1);
            aOff[h][mt] = swz(r, c);
        }
        #pragma unroll
        for (int ntp = 0; ntp < 4; ntp++) {
            int r = cg * 64 + ntp * 16 + (lane & 7) + ((lane >> 4) & 1) * 8;
            int c = h * 2 + ((lane >> 3) & 1);
            bOff[h][ntp] = swz(r, c);
        }
    }

    const int NSTG = K / 32;

    auto issue = [&](int s) {
        const uint32_t base = sb + (s & 3) * GSTG;
        const int k0 = s * 32;
        cpa16(base + offA,        pA_A + k0);
        cpa16(base + 8192 + offA, pW_A + k0);
        cpa16(base + offB,        pA_B + k0);
        cpa16(base + 8192 + offB, pW_B + k0);
    };

    issue(0); CP_COMMIT();
    issue(1); CP_COMMIT();
    issue(2); CP_COMMIT();

    for (int s = 0; s < NSTG; s++) {
        CP_WAIT(2);
        __syncthreads();
        if (s + 3 < NSTG) issue(s + 3);
        CP_COMMIT();

        const uint32_t base = sb + (s & 3) * GSTG;
        #pragma unroll
        for (int h = 0; h < 2; h++) {
            uint32_t a0[4], a1[4];
            ldmx4(base + aOff[h][0], a0);
            ldmx4(base + aOff[h][1], a1);
            #pragma unroll
            for (int ntp = 0; ntp < 4; ntp++) {
                uint32_t bfr[4];
                ldmx4(base + 8192 + bOff[h][ntp], bfr);
                mma16816(acc[0][2*ntp],   a0, bfr[0], bfr[1]);
                mma16816(acc[0][2*ntp+1], a0, bfr[2], bfr[3]);
                mma16816(acc[1][2*ntp],   a1, bfr[0], bfr[1]);
                mma16816(acc[1][2*ntp+1], a1, bfr[2], bfr[3]);
            }
        }
    }

    // ---------------- epilogue ---------------------------------------------
    const int g = lane >> 2, tig = lane & 3;
    const int nBase = n0 + cg * 64;

    float bcol[8][2];
    #pragma unroll
    for (int nt = 0; nt < 8; nt++) {
        bcol[nt][0] = bias[nBase + nt * 8 + tig * 2];
        bcol[nt][1] = bias[nBase + nt * 8 + tig * 2 + 1];
    }

    if (EPI == 0) {
        int part = nBase >> 10;
        int hd   = (nBase & 1023) >> 6;
        if (part < 2) {
            __half* dst = part ? g_Khf : g_Qhf;
            const float sc = part ? 1.0f : 0.125f;
            float fr[4][2];
            #pragma unroll
            for (int nt = 0; nt < 4; nt++) {
                fr[nt][0] = g_freq[nt * 8 + tig * 2];
                fr[nt][1] = g_freq[nt * 8 + tig * 2 + 1];
            }
            #pragma unroll
            for (int mt = 0; mt < 2; mt++)
                #pragma unroll
                for (int half = 0; half < 2; half++) {
                    int m = m0 + wm * 32 + mt * 16 + g + half * 8;
                    int b = m >> 11, sq = m & 2047;
                    size_t rb = (((size_t)b * NH + hd) * NS + sq) * NDH;
                    float pos = (float)posp[b * NS + sq];
                    #pragma unroll
                    for (int nt = 0; nt < 4; nt++) {
                        float r1[2], r2[2];
                        #pragma unroll
                        for (int k = 0; k < 2; k++) {
                            float ang = pos * fr[nt][k];
                            float c, sn;
                            sincosf(ang, &sn, &c);
                            float q1 = acc[mt][nt][half*2 + k]   + bcol[nt][k];
                            float q2 = acc[mt][nt+4][half*2 + k] + bcol[nt+4][k];
                            r1[k] = (q1 * c + q2 * sn) * sc;
                            r2[k] = (q2 * c - q1 * sn) * sc;
                        }
                        int d = nt * 8 + tig * 2;
                        *(uint32_t*)((char*)dst + (rb + d) * 2)      = packh2(r1[0], r1[1]);
                        *(uint32_t*)((char*)dst + (rb + d + 32) * 2) = packh2(r2[0], r2[1]);
                    }
                }
        } else {
            #pragma unroll
            for (int mt = 0; mt < 2; mt++)
                #pragma unroll
                for (int half = 0; half < 2; half++) {
                    int m = m0 + wm * 32 + mt * 16 + g + half * 8;
                    int b = m >> 11, sq = m & 2047;
                    size_t rb = (((size_t)b * NH + hd) * NS + sq) * NDH;
                    #pragma unroll
                    for (int nt = 0; nt < 8; nt++) {
                        int d = nt * 8 + tig * 2;
                        float vx = acc[mt][nt][half*2]   + bcol[nt][0];
                        float vy = acc[mt][nt][half*2+1] + bcol[nt][1];
                        *(uint32_t*)((char*)g_Vhf + (rb + d) * 2) = packh2(vx, vy);
                    }
                }
        }
    } else {
        #pragma unroll
        for (int mt = 0; mt < 2; mt++)
            #pragma unroll
            for (int half = 0; half < 2; half++) {
                int m = m0 + wm * 32 + mt * 16 + g + half * 8;
                #pragma unroll
                for (int nt = 0; nt < 8; nt++) {
                    int n = nBase + nt * 8 + tig * 2;
                    float2 v;
                    v.x = acc[mt][nt][half*2]   + bcol[nt][0];
                    v.y = acc[mt][nt][half*2+1] + bcol[nt][1];
                    *(float2*)(C + (size_t)m * N + n) = v;
                }
            }
    }
}

// ===========================================================================
// fp16 flash attention with half2 softmax + tensor-core row sums.
// 128 threads / 4 warps, 128 q per CTA, warp owns 32 q.
// ===========================================================================
#define AQ 0
#define ASTG_BASE 16384
#define ASTG 16384
#define AT_SMEM (ASTG_BASE + 2*ASTG)    // 49152
#define ONESH2 0x3C003C00u              // half2(1.0, 1.0)

__global__ __launch_bounds__(128, 3) void attn_f16()
{
    extern __shared__ char sma[];
    const uint32_t sb = smem_u32(sma);

    const int tid = threadIdx.x;
    const int warp = tid >> 5, lane = tid & 31;
    const int qt = blockIdx.x, bh = blockIdx.y;

    const size_t qbase  = ((size_t)bh * NS + qt * 128) * NDH;
    const size_t kvbase = (size_t)bh * NS * NDH;

    {
        #pragma unroll
        for (int j = 0; j < 8; j++) {
            int idx = tid + j * 128;
            int row = idx >> 3, c = idx & 7;
            cpa16(sb + AQ + swz128(row, c), g_Qhf + qbase + (size_t)row * NDH + c * 8);
        }
        CP_COMMIT();
    }

    const int rKV = tid >> 3, cKV = tid & 7;
    auto issue_kv = [&](int kt) {
        const uint32_t base = sb + ASTG_BASE + (kt & 1) * ASTG;
        #pragma unroll
        for (int j = 0; j < 4; j++) {
            int row = rKV + j * 16;
            uint32_t o = swz128(row, cKV);
            size_t go = kvbase + (size_t)(kt * 64 + row) * NDH + cKV * 8;
            cpa16(base + o,        g_Khf + go);
            cpa16(base + 8192 + o, g_Vhf + go);
        }
    };
    issue_kv(0); CP_COMMIT();

    uint32_t qOff[4][2];
    #pragma unroll
    for (int kc = 0; kc < 4; kc++)
        #pragma unroll
        for (int mt = 0; mt < 2; mt++) {
            int r = warp * 32 + mt * 16 + (lane & 15);
            int c = kc * 2 + ((lane >> 4) & 1);
            qOff[kc][mt] = swz128(r, c);
        }
    uint32_t kOff[4][4];
    #pragma unroll
    for (int kc = 0; kc < 4; kc++)
        #pragma unroll
        for (int ntp = 0; ntp < 4; ntp++) {
            int r = ntp * 16 + (lane & 7) + ((lane >> 4) & 1) * 8;
            int c = kc * 2 + ((lane >> 3) & 1);
            kOff[kc][ntp] = swz128(r, c);
        }
    uint32_t vOff[4][4];
    #pragma unroll
    for (int kq = 0; kq < 4; kq++)
        #pragma unroll
        for (int dp = 0; dp < 4; dp++) {
            int r = kq * 16 + (lane & 7) + ((lane >> 3) & 1) * 8;
            int c = dp * 2 + ((lane >> 4) & 1);
            vOff[kq][dp] = swz128(r, c);
        }

    float Oa[2][8][4];
    float lacc[2][4];                 // tensor-core row sums (cols identical)
    float mrun[2][2];
    #pragma unroll
    for (int mt = 0; mt < 2; mt++) {
        mrun[mt][0] = -INFINITY; mrun[mt][1] = -INFINITY;
        #pragma unroll
        for (int i = 0; i < 4; i++) lacc[mt][i] = 0.f;
        #pragma unroll
        for (int dt = 0; dt < 8; dt++)
            #pragma unroll
            for (int i = 0; i < 4; i++) Oa[mt][dt][i] = 0.f;
    }

    for (int kt = 0; kt < NS / 64; kt++) {
        CP_WAIT(0);
        __syncthreads();
        if (kt + 1 < NS / 64) issue_kv(kt + 1);
        CP_COMMIT();

        const uint32_t kb = sb + ASTG_BASE + (kt & 1) * ASTG;

        // ---- S = Q K^T ----------------------------------------------------
        float S[2][8][4];
        #pragma unroll
        for (int mt = 0; mt < 2; mt++)
            #pragma unroll
            for (int nt = 0; nt < 8; nt++)
                #pragma unroll
                for (int i = 0; i < 4; i++) S[mt][nt][i] = 0.f;

        #pragma unroll
        for (int kc = 0; kc < 4; kc++) {
            uint32_t q0[4], q1[4];
            ldmx4(sb + AQ + qOff[kc][0], q0);
            ldmx4(sb + AQ + qOff[kc][1], q1);
            #pragma unroll
            for (int ntp = 0; ntp < 4; ntp++) {
                uint32_t kf[4];
                ldmx4(kb + kOff[kc][ntp], kf);
                mma16816(S[0][2*ntp],   q0, kf[0], kf[1]);
                mma16816(S[0][2*ntp+1], q0, kf[2], kf[3]);
                mma16816(S[1][2*ntp],   q1, kf[0], kf[1]);
                mma16816(S[1][2*ntp+1], q1, kf[2], kf[3]);
            }
        }

        // ---- softmax: max (fp32) -> P = ex2.f16x2, packed half2 -----------
        uint32_t P2[2][8][2];
        #pragma unroll
        for (int mt = 0; mt < 2; mt++) {
            float mx0 = -INFINITY, mx1 = -INFINITY;
            #pragma unroll
            for (int j = 0; j < 8; j++) {
                mx0 = fmaxf(mx0, fmaxf(S[mt][j][0], S[mt][j][1]));
                mx1 = fmaxf(mx1, fmaxf(S[mt][j][2], S[mt][j][3]));
            }
            mx0 = fmaxf(mx0, __shfl_xor_sync(0xffffffffu, mx0, 1));
            mx0 = fmaxf(mx0, __shfl_xor_sync(0xffffffffu, mx0, 2));
            mx1 = fmaxf(mx1, __shfl_xor_sync(0xffffffffu, mx1, 1));
            mx1 = fmaxf(mx1, __shfl_xor_sync(0xffffffffu, mx1, 2));
            float nm0 = fmaxf(mrun[mt][0], mx0);
            float nm1 = fmaxf(mrun[mt][1], mx1);
            float a0 = __expf(mrun[mt][0] - nm0);
            float a1 = __expf(mrun[mt][1] - nm1);
            mrun[mt][0] = nm0; mrun[mt][1] = nm1;
            float nb0 = nm0 * LOG2E, nb1 = nm1 * LOG2E;
            #pragma unroll
            for (int j = 0; j < 8; j++) {
                float t0 = fmaf(S[mt][j][0], LOG2E, -nb0);
                float t1 = fmaf(S[mt][j][1], LOG2E, -nb0);
                P2[mt][j][0] = ex2h2(packh2(t0, t1));
                float t2 = fmaf(S[mt][j][2], LOG2E, -nb1);
                float t3 = fmaf(S[mt][j][3], LOG2E, -nb1);
                P2[mt][j][1] = ex2h2(packh2(t2, t3));
            }
            // rescale O and l accumulators
            #pragma unroll
            for (int dt = 0; dt < 8; dt++) {
                Oa[mt][dt][0] *= a0; Oa[mt][dt][1] *= a0;
                Oa[mt][dt][2] *= a1; Oa[mt][dt][3] *= a1;
            }
            lacc[mt][0] *= a0; lacc[mt][1] *= a0;
            lacc[mt][2] *= a1; lacc[mt][3] *= a1;
        }

        // ---- O += P V ; l += P @ ones -------------------------------------
        #pragma unroll
        for (int kq = 0; kq < 4; kq++) {
            uint32_t pa0[4] = {P2[0][2*kq][0], P2[0][2*kq][1],
                               P2[0][2*kq+1][0], P2[0][2*kq+1][1]};
            uint32_t pa1[4] = {P2[1][2*kq][0], P2[1][2*kq][1],
                               P2[1][2*kq+1][0], P2[1][2*kq+1][1]};
            mma16816(lacc[0], pa0, ONESH2, ONESH2);
            mma16816(lacc[1], pa1, ONESH2, ONESH2);
            #pragma unroll
            for (int dp = 0; dp < 4; dp++) {
                uint32_t vf[4];
                ldmx4t(kb + 8192 + vOff[kq][dp], vf);
                mma16816(Oa[0][2*dp],   pa0, vf[0], vf[1]);
                mma16816(Oa[0][2*dp+1], pa0, vf[2], vf[3]);
                mma16816(Oa[1][2*dp],   pa1, vf[0], vf[1]);
                mma16816(Oa[1][2*dp+1], pa1, vf[2], vf[3]);
            }
        }
    }

    // ---- epilogue: O /= l -> ctx fp16 [B,S,H*Dh] --------------------------
    const int b = bh >> 4, h = bh & 15;
    const int g = lane >> 2, tg = lane & 3;
    #pragma unroll
    for (int mt = 0; mt < 2; mt++)
        #pragma unroll
        for (int half = 0; half < 2; half++) {
            int q = qt * 128 + warp * 32 + mt * 16 + g + half * 8;
            float inv = 1.0f / lacc[mt][half*2];
            size_t rb = ((size_t)b * NS + q) * ND + h * NDH;
            #pragma unroll
            for (int dt = 0; dt < 8; dt++) {
                float vx = Oa[mt][dt][half*2]   * inv;
                float vy = Oa[mt][dt][half*2+1] * inv;
                size_t o = rb + dt * 8 + tg * 2;
                *(uint32_t*)((char*)g_ctxhf + o * 2) = packh2(vx, vy);
            }
        }
}

// ===========================================================================
extern "C" void kernel_launch(void* const* d_in, const int* in_sizes, int n_in,
                              void* d_out, int out_size)
{
    (void)in_sizes; (void)n_in; (void)out_size;
    const float* x      = (const float*)d_in[0];
    const int*   p      = (const int*)d_in[1];
    const float* Wqkv_w = (const float*)d_in[2];
    const float* Wqkv_b = (const float*)d_in[3];
    const float* Wo_w   = (const float*)d_in[4];
    const float* Wo_b   = (const float*)d_in[5];
    float* out = (float*)d_out;

    cudaFuncSetAttribute(gemm_f16<0>,
                         cudaFuncAttributeMaxDynamicSharedMemorySize, GK_SMEM);
    cudaFuncSetAttribute(gemm_f16<1>,
                         cudaFuncAttributeMaxDynamicSharedMemorySize, GK_SMEM);
    cudaFuncSetAttribute(attn_f16,
                         cudaFuncAttributeMaxDynamicSharedMemorySize, AT_SMEM);

    __half *xh, *wqh, *woh, *ctxh;
    cudaGetSymbolAddress((void**)&xh,   g_xhf);
    cudaGetSymbolAddress((void**)&wqh,  g_wqhf);
    cudaGetSymbolAddress((void**)&woh,  g_wohf);
    cudaGetSymbolAddress((void**)&ctxh, g_ctxhf);

    freq_kernel<<<1, 32>>>();

    int n4x = MT * ND / 4, n4wq = 3 * ND * ND / 4, n4wo = ND * ND / 4;
    int n4t = n4x + n4wq + n4wo;
    conv_all<<<(n4t + 255) / 256, 256>>>(
        (const float4*)x, (const float4*)Wqkv_w, (const float4*)Wo_w,
        (uint2*)xh, (uint2*)wqh, (uint2*)woh, n4x, n4wq, n4wo);

    dim3 g1(3 * ND / 128, MT / 128);
    gemm_f16<0><<<g1, 256, GK_SMEM>>>(xh, wqh, Wqkv_b, p, nullptr, 3 * ND, ND);

    attn_f16<<<dim3(NS / 128, NB * NH), 128, AT_SMEM>>>();

    dim3 g2(ND / 128, MT / 128);
    gemm_f16<1><<<g2, 256, GK_SMEM>>>(ctxh, woh, Wo_b, nullptr, out, ND, ND);
}

// round 11
// speedup vs baseline: 3.0761x; 1.0218x over previous
#include <cuda_runtime.h>
#include <cuda_fp16.h>
#include <math.h>
#include <stdint.h>

#define NB   4
#define NS   2048
#define ND   1024
#define NH   16
#define NDH  64
#define MT   (NB*NS)          // 8192 rows
#define QKV_ELEMS ((size_t)NB*NH*NS*NDH)
#define LOG2E 1.4426950408889634f

// ---------------- scratch (device globals: no allocation allowed) ----------
__device__ __half g_Qhf[QKV_ELEMS];           // post-RoPE, *0.125, fp16
__device__ __half g_Khf[QKV_ELEMS];
__device__ __half g_Vhf[QKV_ELEMS];
__device__ __half g_xhf[(size_t)MT*ND];
__device__ __half g_wqhf[(size_t)3*ND*ND];
__device__ __half g_wohf[(size_t)ND*ND];
__device__ __half g_ctxhf[(size_t)MT*ND];
__device__ float  g_freq[32];                 // 10000^(-i/32), fp32 (from double)

// ======================= helpers ===========================================
__device__ __forceinline__ uint32_t smem_u32(const void* p) {
    uint32_t a;
    asm("{ .reg .u64 t; cvta.to.shared.u64 t, %1; cvt.u32.u64 %0, t; }"
        : "=r"(a) : "l"(p));
    return a;
}
__device__ __forceinline__ void ldmx4(uint32_t addr, uint32_t r[4]) {
    asm volatile("ldmatrix.sync.aligned.m8n8.x4.shared.b16 {%0,%1,%2,%3}, [%4];"
                 : "=r"(r[0]), "=r"(r[1]), "=r"(r[2]), "=r"(r[3]) : "r"(addr));
}
__device__ __forceinline__ void ldmx4t(uint32_t addr, uint32_t r[4]) {
    asm volatile("ldmatrix.sync.aligned.m8n8.x4.trans.shared.b16 {%0,%1,%2,%3}, [%4];"
                 : "=r"(r[0]), "=r"(r[1]), "=r"(r[2]), "=r"(r[3]) : "r"(addr));
}
__device__ __forceinline__ void mma16816(float c[4], const uint32_t a[4],
                                         uint32_t b0, uint32_t b1) {
    asm("mma.sync.aligned.m16n8k16.row.col.f32.f16.f16.f32 "
        "{%0,%1,%2,%3}, {%4,%5,%6,%7}, {%8,%9}, {%0,%1,%2,%3};"
        : "+f"(c[0]), "+f"(c[1]), "+f"(c[2]), "+f"(c[3])
        : "r"(a[0]), "r"(a[1]), "r"(a[2]), "r"(a[3]), "r"(b0), "r"(b1));
}
__device__ __forceinline__ uint32_t packh2(float x, float y) {
    __half2 h = __floats2half2_rn(x, y);
    return *(uint32_t*)&h;
}
__device__ __forceinline__ uint32_t ex2h2(uint32_t x) {
    uint32_t d;
    asm("ex2.approx.f16x2 %0, %1;" : "=r"(d) : "r"(x));
    return d;
}
// XOR swizzle: 16B chunk c of 64B row
__device__ __forceinline__ uint32_t swz(int row, int c) {
    return (uint32_t)(row * 64 + ((c ^ ((row >> 1) & 3)) * 16));
}
// XOR swizzle for 128B rows
__device__ __forceinline__ uint32_t swz128(int row, int c) {
    return (uint32_t)(row * 128 + ((c ^ (row & 7)) * 16));
}
__device__ __forceinline__ void cpa16(uint32_t dst, const void* src) {
    asm volatile("cp.async.cg.shared.global [%0], [%1], 16;"
                 :: "r"(dst), "l"(src));
}
#define CP_COMMIT()  asm volatile("cp.async.commit_group;")
#define CP_WAIT(n)   asm volatile("cp.async.wait_group %0;" :: "n"(n))

// ===========================================================================
// setup: RoPE freqs (double-precision exp, matching jnp fp32-rounded values)
// ===========================================================================
__global__ void freq_kernel()
{
    int i = threadIdx.x;
    if (i < 32)
        g_freq[i] = (float)exp(-(double)i * (9.210340371976184 / 32.0));
}

// ===========================================================================
// merged fp32 -> fp16 converts for x, Wqkv, Wo
// ===========================================================================
__global__ void conv_all(const float4* __restrict__ x,
                         const float4* __restrict__ wq,
                         const float4* __restrict__ wo,
                         uint2* __restrict__ xh, uint2* __restrict__ wqh,
                         uint2* __restrict__ woh,
                         int n4x, int n4wq, int n4wo)
{
    int i = blockIdx.x * blockDim.x + threadIdx.x;
    const float4* src; uint2* dst; int idx;
    if (i < n4x)                 { src = x;  dst = xh;  idx = i; }
    else if (i < n4x + n4wq)     { src = wq; dst = wqh; idx = i - n4x; }
    else if (i < n4x + n4wq + n4wo) { src = wo; dst = woh; idx = i - n4x - n4wq; }
    else return;
    float4 v = src[idx];
    dst[idx] = make_uint2(packh2(v.x, v.y), packh2(v.z, v.w));
}

// ===========================================================================
// fp16 GEMM (unchanged from passing R9/R10): cp.async 4-stage pipeline.
// EPI==0: fused QKV epilogue — RoPE(Q,K) -> fp16 (Q *0.125), V -> fp16.
// EPI==1: fp32 C.
// ===========================================================================
#define GSTG 16384
#define GK_SMEM (4*GSTG)

template<int EPI>
__global__ __launch_bounds__(256, 2) void gemm_f16(
    const __half* __restrict__ A, const __half* __restrict__ W,
    const float* __restrict__ bias, const int* __restrict__ posp,
    float* __restrict__ C, int N, int K)
{
    extern __shared__ char smc[];
    const uint32_t sb = smem_u32(smc);

    const int tid  = threadIdx.x;
    const int warp = tid >> 5, lane = tid & 31;
    const int wm = warp & 3, cg = warp >> 2;
    const int m0 = blockIdx.y * 128, n0 = blockIdx.x * 128;

    const int rowA = tid >> 2, cA = tid & 3;
    const int rowB = (tid + 256) >> 2, cB = tid & 3;
    const uint32_t offA = swz(rowA, cA), offB = swz(rowB, cB);
    const __half* pA_A = A + (size_t)(m0 + rowA) * K + cA * 8;
    const __half* pW_A = W + (size_t)(n0 + rowA) * K + cA * 8;
    const __half* pA_B = A + (size_t)(m0 + rowB) * K + cB * 8;
    const __half* pW_B = W + (size_t)(n0 + rowB) * K + cB * 8;

    float acc[2][8][4];
    #pragma unroll
    for (int mt = 0; mt < 2; mt++)
        #pragma unroll
        for (int nt = 0; nt < 8; nt++)
            #pragma unroll
            for (int i = 0; i < 4; i++) acc[mt][nt][i] = 0.f;

    uint32_t aOff[2][2], bOff[2][4];
    #pragma unroll
    for (int h = 0; h < 2; h++) {
        #pragma unroll
        for (int mt = 0; mt < 2; mt++) {
            int r = wm * 32 + mt * 16 + (lane & 15);
            int c = h * 2 + ((lane >> 4) & 1);
            aOff[h][mt] = swz(r, c);
        }
        #pragma unroll
        for (int ntp = 0; ntp < 4; ntp++) {
            int r = cg * 64 + ntp * 16 + (lane & 7) + ((lane >> 4) & 1) * 8;
            int c = h * 2 + ((lane >> 3) & 1);
            bOff[h][ntp] = swz(r, c);
        }
    }

    const int NSTG = K / 32;

    auto issue = [&](int s) {
        const uint32_t base = sb + (s & 3) * GSTG;
        const int k0 = s * 32;
        cpa16(base + offA,        pA_A + k0);
        cpa16(base + 8192 + offA, pW_A + k0);
        cpa16(base + offB,        pA_B + k0);
        cpa16(base + 8192 + offB, pW_B + k0);
    };

    issue(0); CP_COMMIT();
    issue(1); CP_COMMIT();
    issue(2); CP_COMMIT();

    for (int s = 0; s < NSTG; s++) {
        CP_WAIT(2);
        __syncthreads();
        if (s + 3 < NSTG) issue(s + 3);
        CP_COMMIT();

        const uint32_t base = sb + (s & 3) * GSTG;
        #pragma unroll
        for (int h = 0; h < 2; h++) {
            uint32_t a0[4], a1[4];
            ldmx4(base + aOff[h][0], a0);
            ldmx4(base + aOff[h][1], a1);
            #pragma unroll
            for (int ntp = 0; ntp < 4; ntp++) {
                uint32_t bfr[4];
                ldmx4(base + 8192 + bOff[h][ntp], bfr);
                mma16816(acc[0][2*ntp],   a0, bfr[0], bfr[1]);
                mma16816(acc[0][2*ntp+1], a0, bfr[2], bfr[3]);
                mma16816(acc[1][2*ntp],   a1, bfr[0], bfr[1]);
                mma16816(acc[1][2*ntp+1], a1, bfr[2], bfr[3]);
            }
        }
    }

    // ---------------- epilogue ---------------------------------------------
    const int g = lane >> 2, tig = lane & 3;
    const int nBase = n0 + cg * 64;

    float bcol[8][2];
    #pragma unroll
    for (int nt = 0; nt < 8; nt++) {
        bcol[nt][0] = bias[nBase + nt * 8 + tig * 2];
        bcol[nt][1] = bias[nBase + nt * 8 + tig * 2 + 1];
    }

    if (EPI == 0) {
        int part = nBase >> 10;
        int hd   = (nBase & 1023) >> 6;
        if (part < 2) {
            __half* dst = part ? g_Khf : g_Qhf;
            const float sc = part ? 1.0f : 0.125f;
            float fr[4][2];
            #pragma unroll
            for (int nt = 0; nt < 4; nt++) {
                fr[nt][0] = g_freq[nt * 8 + tig * 2];
                fr[nt][1] = g_freq[nt * 8 + tig * 2 + 1];
            }
            #pragma unroll
            for (int mt = 0; mt < 2; mt++)
                #pragma unroll
                for (int half = 0; half < 2; half++) {
                    int m = m0 + wm * 32 + mt * 16 + g + half * 8;
                    int b = m >> 11, sq = m & 2047;
                    size_t rb = (((size_t)b * NH + hd) * NS + sq) * NDH;
                    float pos = (float)posp[b * NS + sq];
                    #pragma unroll
                    for (int nt = 0; nt < 4; nt++) {
                        float r1[2], r2[2];
                        #pragma unroll
                        for (int k = 0; k < 2; k++) {
                            float ang = pos * fr[nt][k];
                            float c, sn;
                            sincosf(ang, &sn, &c);
                            float q1 = acc[mt][nt][half*2 + k]   + bcol[nt][k];
                            float q2 = acc[mt][nt+4][half*2 + k] + bcol[nt+4][k];
                            r1[k] = (q1 * c + q2 * sn) * sc;
                            r2[k] = (q2 * c - q1 * sn) * sc;
                        }
                        int d = nt * 8 + tig * 2;
                        *(uint32_t*)((char*)dst + (rb + d) * 2)      = packh2(r1[0], r1[1]);
                        *(uint32_t*)((char*)dst + (rb + d + 32) * 2) = packh2(r2[0], r2[1]);
                    }
                }
        } else {
            #pragma unroll
            for (int mt = 0; mt < 2; mt++)
                #pragma unroll
                for (int half = 0; half < 2; half++) {
                    int m = m0 + wm * 32 + mt * 16 + g + half * 8;
                    int b = m >> 11, sq = m & 2047;
                    size_t rb = (((size_t)b * NH + hd) * NS + sq) * NDH;
                    #pragma unroll
                    for (int nt = 0; nt < 8; nt++) {
                        int d = nt * 8 + tig * 2;
                        float vx = acc[mt][nt][half*2]   + bcol[nt][0];
                        float vy = acc[mt][nt][half*2+1] + bcol[nt][1];
                        *(uint32_t*)((char*)g_Vhf + (rb + d) * 2) = packh2(vx, vy);
                    }
                }
        }
    } else {
        #pragma unroll
        for (int mt = 0; mt < 2; mt++)
            #pragma unroll
            for (int half = 0; half < 2; half++) {
                int m = m0 + wm * 32 + mt * 16 + g + half * 8;
                #pragma unroll
                for (int nt = 0; nt < 8; nt++) {
                    int n = nBase + nt * 8 + tig * 2;
                    float2 v;
                    v.x = acc[mt][nt][half*2]   + bcol[nt][0];
                    v.y = acc[mt][nt][half*2+1] + bcol[nt][1];
                    *(float2*)(C + (size_t)m * N + n) = v;
                }
            }
    }
}

// ===========================================================================
// fp16 flash attention: hoisted Q fragments, 3-stage cp.async KV ring,
// warp-vote rescale skip. 128 threads / 4 warps, 128 q per CTA.
// smem: Q 16KB | 3 stages @16KB (K 8KB | V 8KB) = 64KB.
// ===========================================================================
#define AQ 0
#define ASTG_BASE 16384
#define ASTG 16384
#define AT_SMEM (ASTG_BASE + 3*ASTG)    // 65536
#define ONESH2 0x3C003C00u              // half2(1.0, 1.0)
#define NT (NS/64)                      // 32 kv tiles

__global__ __launch_bounds__(128, 2) void attn_f16()
{
    extern __shared__ char sma[];
    const uint32_t sb = smem_u32(sma);

    const int tid = threadIdx.x;
    const int warp = tid >> 5, lane = tid & 31;
    const int qt = blockIdx.x, bh = blockIdx.y;

    const size_t qbase  = ((size_t)bh * NS + qt * 128) * NDH;
    const size_t kvbase = (size_t)bh * NS * NDH;

    // ---- issue Q fill -----------------------------------------------------
    {
        #pragma unroll
        for (int j = 0; j < 8; j++) {
            int idx = tid + j * 128;
            int row = idx >> 3, c = idx & 7;
            cpa16(sb + AQ + swz128(row, c), g_Qhf + qbase + (size_t)row * NDH + c * 8);
        }
        CP_COMMIT();
    }

    const int rKV = tid >> 3, cKV = tid & 7;
    auto issue_kv = [&](int kt) {
        const uint32_t base = sb + ASTG_BASE + (kt % 3) * ASTG;
        #pragma unroll
        for (int j = 0; j < 4; j++) {
            int row = rKV + j * 16;
            uint32_t o = swz128(row, cKV);
            size_t go = kvbase + (size_t)(kt * 64 + row) * NDH + cKV * 8;
            cpa16(base + o,        g_Khf + go);
            cpa16(base + 8192 + o, g_Vhf + go);
        }
    };
    issue_kv(0); CP_COMMIT();
    issue_kv(1); CP_COMMIT();

    // ---- fragment smem offsets --------------------------------------------
    uint32_t qOff[4][2];
    #pragma unroll
    for (int kc = 0; kc < 4; kc++)
        #pragma unroll
        for (int mt = 0; mt < 2; mt++) {
            int r = warp * 32 + mt * 16 + (lane & 15);
            int c = kc * 2 + ((lane >> 4) & 1);
            qOff[kc][mt] = swz128(r, c);
        }
    uint32_t kOff[4][4];
    #pragma unroll
    for (int kc = 0; kc < 4; kc++)
        #pragma unroll
        for (int ntp = 0; ntp < 4; ntp++) {
            int r = ntp * 16 + (lane & 7) + ((lane >> 4) & 1) * 8;
            int c = kc * 2 + ((lane >> 3) & 1);
            kOff[kc][ntp] = swz128(r, c);
        }
    uint32_t vOff[4][4];
    #pragma unroll
    for (int kq = 0; kq < 4; kq++)
        #pragma unroll
        for (int dp = 0; dp < 4; dp++) {
            int r = kq * 16 + (lane & 7) + ((lane >> 3) & 1) * 8;
            int c = dp * 2 + ((lane >> 4) & 1);
            vOff[kq][dp] = swz128(r, c);
        }

    // ---- wait for Q, hoist Q fragments into registers ---------------------
    CP_WAIT(2);            // Q done (kv0, kv1 may still be in flight)
    __syncthreads();
    uint32_t qf[4][2][4];
    #pragma unroll
    for (int kc = 0; kc < 4; kc++) {
        ldmx4(sb + AQ + qOff[kc][0], qf[kc][0]);
        ldmx4(sb + AQ + qOff[kc][1], qf[kc][1]);
    }

    float Oa[2][8][4];
    float lacc[2][4];
    float mrun[2][2];
    #pragma unroll
    for (int mt = 0; mt < 2; mt++) {
        mrun[mt][0] = -INFINITY; mrun[mt][1] = -INFINITY;
        #pragma unroll
        for (int i = 0; i < 4; i++) lacc[mt][i] = 0.f;
        #pragma unroll
        for (int dt = 0; dt < 8; dt++)
            #pragma unroll
            for (int i = 0; i < 4; i++) Oa[mt][dt][i] = 0.f;
    }

    for (int kt = 0; kt < NT; kt++) {
        if (kt + 1 < NT) { CP_WAIT(1); } else { CP_WAIT(0); }
        __syncthreads();
        if (kt + 2 < NT) { issue_kv(kt + 2); CP_COMMIT(); }

        const uint32_t kb = sb + ASTG_BASE + (kt % 3) * ASTG;

        // ---- S = Q K^T ----------------------------------------------------
        float S[2][8][4];
        #pragma unroll
        for (int mt = 0; mt < 2; mt++)
            #pragma unroll
            for (int nt = 0; nt < 8; nt++)
                #pragma unroll
                for (int i = 0; i < 4; i++) S[mt][nt][i] = 0.f;

        #pragma unroll
        for (int kc = 0; kc < 4; kc++) {
            #pragma unroll
            for (int ntp = 0; ntp < 4; ntp++) {
                uint32_t kf[4];
                ldmx4(kb + kOff[kc][ntp], kf);
                mma16816(S[0][2*ntp],   qf[kc][0], kf[0], kf[1]);
                mma16816(S[0][2*ntp+1], qf[kc][0], kf[2], kf[3]);
                mma16816(S[1][2*ntp],   qf[kc][1], kf[0], kf[1]);
                mma16816(S[1][2*ntp+1], qf[kc][1], kf[2], kf[3]);
            }
        }

        // ---- softmax: fp32 max -> half2 exp; vote-skip identity rescale ---
        uint32_t P2[2][8][2];
        #pragma unroll
        for (int mt = 0; mt < 2; mt++) {
            float mx0 = -INFINITY, mx1 = -INFINITY;
            #pragma unroll
            for (int j = 0; j < 8; j++) {
                mx0 = fmaxf(mx0, fmaxf(S[mt][j][0], S[mt][j][1]));
                mx1 = fmaxf(mx1, fmaxf(S[mt][j][2], S[mt][j][3]));
            }
            mx0 = fmaxf(mx0, __shfl_xor_sync(0xffffffffu, mx0, 1));
            mx0 = fmaxf(mx0, __shfl_xor_sync(0xffffffffu, mx0, 2));
            mx1 = fmaxf(mx1, __shfl_xor_sync(0xffffffffu, mx1, 1));
            mx1 = fmaxf(mx1, __shfl_xor_sync(0xffffffffu, mx1, 2));
            float nm0 = fmaxf(mrun[mt][0], mx0);
            float nm1 = fmaxf(mrun[mt][1], mx1);
            bool grew = (nm0 > mrun[mt][0]) || (nm1 > mrun[mt][1]);
            if (__any_sync(0xffffffffu, grew)) {
                float a0 = __expf(mrun[mt][0] - nm0);
                float a1 = __expf(mrun[mt][1] - nm1);
                #pragma unroll
                for (int dt = 0; dt < 8; dt++) {
                    Oa[mt][dt][0] *= a0; Oa[mt][dt][1] *= a0;
                    Oa[mt][dt][2] *= a1; Oa[mt][dt][3] *= a1;
                }
                lacc[mt][0] *= a0; lacc[mt][1] *= a0;
                lacc[mt][2] *= a1; lacc[mt][3] *= a1;
            }
            mrun[mt][0] = nm0; mrun[mt][1] = nm1;
            float nb0 = nm0 * LOG2E, nb1 = nm1 * LOG2E;
            #pragma unroll
            for (int j = 0; j < 8; j++) {
                float t0 = fmaf(S[mt][j][0], LOG2E, -nb0);
                float t1 = fmaf(S[mt][j][1], LOG2E, -nb0);
                P2[mt][j][0] = ex2h2(packh2(t0, t1));
                float t2 = fmaf(S[mt][j][2], LOG2E, -nb1);
                float t3 = fmaf(S[mt][j][3], LOG2E, -nb1);
                P2[mt][j][1] = ex2h2(packh2(t2, t3));
            }
        }

        // ---- O += P V ; l += P @ ones -------------------------------------
        #pragma unroll
        for (int kq = 0; kq < 4; kq++) {
            uint32_t pa0[4] = {P2[0][2*kq][0], P2[0][2*kq][1],
                               P2[0][2*kq+1][0], P2[0][2*kq+1][1]};
            uint32_t pa1[4] = {P2[1][2*kq][0], P2[1][2*kq][1],
                               P2[1][2*kq+1][0], P2[1][2*kq+1][1]};
            mma16816(lacc[0], pa0, ONESH2, ONESH2);
            mma16816(lacc[1], pa1, ONESH2, ONESH2);
            #pragma unroll
            for (int dp = 0; dp < 4; dp++) {
                uint32_t vf[4];
                ldmx4t(kb + 8192 + vOff[kq][dp], vf);
                mma16816(Oa[0][2*dp],   pa0, vf[0], vf[1]);
                mma16816(Oa[0][2*dp+1], pa0, vf[2], vf[3]);
                mma16816(Oa[1][2*dp],   pa1, vf[0], vf[1]);
                mma16816(Oa[1][2*dp+1], pa1, vf[2], vf[3]);
            }
        }
    }

    // ---- epilogue: O /= l -> ctx fp16 [B,S,H*Dh] --------------------------
    const int b = bh >> 4, h = bh & 15;
    const int g = lane >> 2, tg = lane & 3;
    #pragma unroll
    for (int mt = 0; mt < 2; mt++)
        #pragma unroll
        for (int half = 0; half < 2; half++) {
            int q = qt * 128 + warp * 32 + mt * 16 + g + half * 8;
            float inv = 1.0f / lacc[mt][half*2];
            size_t rb = ((size_t)b * NS + q) * ND + h * NDH;
            #pragma unroll
            for (int dt = 0; dt < 8; dt++) {
                float vx = Oa[mt][dt][half*2]   * inv;
                float vy = Oa[mt][dt][half*2+1] * inv;
                size_t o = rb + dt * 8 + tg * 2;
                *(uint32_t*)((char*)g_ctxhf + o * 2) = packh2(vx, vy);
            }
        }
}

// ===========================================================================
extern "C" void kernel_launch(void* const* d_in, const int* in_sizes, int n_in,
                              void* d_out, int out_size)
{
    (void)in_sizes; (void)n_in; (void)out_size;
    const float* x      = (const float*)d_in[0];
    const int*   p      = (const int*)d_in[1];
    const float* Wqkv_w = (const float*)d_in[2];
    const float* Wqkv_b = (const float*)d_in[3];
    const float* Wo_w   = (const float*)d_in[4];
    const float* Wo_b   = (const float*)d_in[5];
    float* out = (float*)d_out;

    cudaFuncSetAttribute(gemm_f16<0>,
                         cudaFuncAttributeMaxDynamicSharedMemorySize, GK_SMEM);
    cudaFuncSetAttribute(gemm_f16<1>,
                         cudaFuncAttributeMaxDynamicSharedMemorySize, GK_SMEM);
    cudaFuncSetAttribute(attn_f16,
                         cudaFuncAttributeMaxDynamicSharedMemorySize, AT_SMEM);

    __half *xh, *wqh, *woh, *ctxh;
    cudaGetSymbolAddress((void**)&xh,   g_xhf);
    cudaGetSymbolAddress((void**)&wqh,  g_wqhf);
    cudaGetSymbolAddress((void**)&woh,  g_wohf);
    cudaGetSymbolAddress((void**)&ctxh, g_ctxhf);

    freq_kernel<<<1, 32>>>();

    int n4x = MT * ND / 4, n4wq = 3 * ND * ND / 4, n4wo = ND * ND / 4;
    int n4t = n4x + n4wq + n4wo;
    conv_all<<<(n4t + 255) / 256, 256>>>(
        (const float4*)x, (const float4*)Wqkv_w, (const float4*)Wo_w,
        (uint2*)xh, (uint2*)wqh, (uint2*)woh, n4x, n4wq, n4wo);

    dim3 g1(3 * ND / 128, MT / 128);
    gemm_f16<0><<<g1, 256, GK_SMEM>>>(xh, wqh, Wqkv_b, p, nullptr, 3 * ND, ND);

    attn_f16<<<dim3(NS / 128, NB * NH), 128, AT_SMEM>>>();

    dim3 g2(ND / 128, MT / 128);
    gemm_f16<1><<<g2, 256, GK_SMEM>>>(ctxh, woh, Wo_b, nullptr, out, ND, ND);
}